// round 13
// baseline (speedup 1.0000x reference)
#include <cuda_runtime.h>
#include <math.h>

// ---------------- scratch (device globals; no allocation allowed) ----------------
__device__ float g_x1[1024 * 16 * 48 * 60];   // conv1 out
__device__ float g_x2[1024 * 16 * 24 * 30];   // conv2 out
__device__ float g_x3[1024 * 16 * 12 * 15];   // conv3 out (= tokens x 2880)
__device__ float g_x [1024 * 256];            // residual stream
__device__ float g_xn[1024 * 256];            // ln1 output
__device__ float g_c [1024 * 768];            // qkv
__device__ float g_h [1024 * 1024];           // ffn hidden
__device__ float g_sp[4 * 1024 * 1024];       // split-K partials
__device__ unsigned g_cnt[512];               // per-tile arrival counters
__device__ double g_part[512];                // partial sums / sumsq

// ---------------- helpers ----------------
__device__ __forceinline__ unsigned f2tf(float f) {
    unsigned u;
    asm("cvt.rna.tf32.f32 %0, %1;" : "=r"(u) : "f"(f));
    return u;
}
__device__ __forceinline__ void mma_tf32(float c[4], unsigned a0, unsigned a1,
                                         unsigned a2, unsigned a3,
                                         unsigned b0, unsigned b1) {
    asm volatile(
        "mma.sync.aligned.m16n8k8.row.col.f32.tf32.tf32.f32 "
        "{%0,%1,%2,%3}, {%4,%5,%6,%7}, {%8,%9}, {%0,%1,%2,%3};\n"
        : "+f"(c[0]), "+f"(c[1]), "+f"(c[2]), "+f"(c[3])
        : "r"(a0), "r"(a1), "r"(a2), "r"(a3), "r"(b0), "r"(b1));
}
__device__ __forceinline__ void cpasync16(const void* smem_dst, const void* gsrc) {
    unsigned s = (unsigned)__cvta_generic_to_shared(smem_dst);
    asm volatile("cp.async.cg.shared.global [%0], [%1], 16;" :: "r"(s), "l"(gsrc));
}
__device__ __forceinline__ void cp_commit() {
    asm volatile("cp.async.commit_group;");
}
template <int N>
__device__ __forceinline__ void cp_wait() {
    asm volatile("cp.async.wait_group %0;" :: "n"(N));
}

// ---------------- conv1: fp32 direct (CIN=3) — measured-best version ------------
template <int CIN>
__global__ void __launch_bounds__(256) conv_k(
    const float* __restrict__ in, const float* __restrict__ w,
    const float* __restrict__ bias, float* __restrict__ out,
    int Hin, int Win, int Hout, int Wout) {
    __shared__ float ws[CIN * 16 * 16];   // [widx][co]
    __shared__ float bs[16];
    for (int i = threadIdx.x; i < CIN * 16 * 16; i += blockDim.x) {
        int widx = i >> 4, co = i & 15;
        ws[i] = w[co * CIN * 16 + widx];
    }
    if (threadIdx.x < 16) bs[threadIdx.x] = bias[threadIdx.x];
    __syncthreads();

    const int wg = (Wout + 3) >> 2;
    int idx = blockIdx.x * blockDim.x + threadIdx.x;
    int owg = idx % wg;
    int oh  = (idx / wg) % Hout;
    int n   = idx / (wg * Hout);
    if (n >= 1024) return;

    float acc[16][4];
    #pragma unroll
    for (int co = 0; co < 16; co++)
        #pragma unroll
        for (int p = 0; p < 4; p++) acc[co][p] = 0.f;

    const float* inp = in + n * CIN * Hin * Win;
    const int iwb = owg * 8 - 1;
    #pragma unroll 1
    for (int ci = 0; ci < CIN; ci++) {
        #pragma unroll
        for (int kh = 0; kh < 4; kh++) {
            int ih = oh * 2 - 1 + kh;
            if (ih < 0 || ih >= Hin) continue;
            const float* irow = inp + (ci * Hin + ih) * Win;
            float vin[10];
            #pragma unroll
            for (int j = 0; j < 10; j++) {
                int iw = iwb + j;
                vin[j] = (iw >= 0 && iw < Win) ? irow[iw] : 0.f;
            }
            #pragma unroll
            for (int kw = 0; kw < 4; kw++) {
                int widx = (ci * 4 + kh) * 4 + kw;
                const float4* w4 = (const float4*)&ws[widx << 4];
                float4 w0 = w4[0], w1 = w4[1], w2 = w4[2], w3 = w4[3];
                #pragma unroll
                for (int p = 0; p < 4; p++) {
                    float v = vin[2 * p + kw];
                    acc[0][p]  += w0.x * v; acc[1][p]  += w0.y * v;
                    acc[2][p]  += w0.z * v; acc[3][p]  += w0.w * v;
                    acc[4][p]  += w1.x * v; acc[5][p]  += w1.y * v;
                    acc[6][p]  += w1.z * v; acc[7][p]  += w1.w * v;
                    acc[8][p]  += w2.x * v; acc[9][p]  += w2.y * v;
                    acc[10][p] += w2.z * v; acc[11][p] += w2.w * v;
                    acc[12][p] += w3.x * v; acc[13][p] += w3.y * v;
                    acc[14][p] += w3.z * v; acc[15][p] += w3.w * v;
                }
            }
        }
    }
    int obase = n * 16 * Hout * Wout;
    #pragma unroll
    for (int co = 0; co < 16; co++) {
        #pragma unroll
        for (int p = 0; p < 4; p++) {
            int ow = owg * 4 + p;
            if (ow < Wout)
                out[obase + (co * Hout + oh) * Wout + ow] = fmaxf(acc[co][p] + bs[co], 0.f);
        }
    }
}

// ---------------- tensorized conv (CIN=16, COUT=16, 4x4, stride2, pad1) --------
// Implicit GEMM: M = Hout*Wout pixels (one image per block), N=16, K=256.
// Input staged per 2-ci group into halo-padded SMEM plane (tf32-RNA at staging):
// every im2col fragment access = one unpredicated LDS at rowoff + off_k.
template <int Hin, int Win, int Hout, int Wout, int NW>
__global__ void __launch_bounds__(NW * 32) convt_k(
    const float* __restrict__ in, const float* __restrict__ w,
    const float* __restrict__ bias, float* __restrict__ out) {
    constexpr int HS = Hin + 2, WS = Win + 2;
    constexpr int PLANE = HS * WS;
    constexpr int M = Hout * Wout;
    constexpr int MT_TOT = (M + 15) / 16;
    constexpr int MT_PW = (MT_TOT + NW - 1) / NW;

    __shared__ unsigned sIn[2 * PLANE];     // 2 halo planes, tf32 bits
    __shared__ unsigned Bw[256 * 17];       // weights: [k][co], stride 17

    const int n = blockIdx.x;
    const int t = threadIdx.x;
    const int warp = t >> 5, lane = t & 31;
    const int g = lane >> 2, tig = lane & 3;

    // stage weights (coalesced read; SMEM stride-17 writes are conflict-free)
    for (int i = t; i < 256 * 16; i += NW * 32) {
        int co = i >> 8, k = i & 255;
        Bw[k * 17 + co] = f2tf(w[i]);
    }

    // per-warp row offsets (halo coords): rowoff = (oh*2)*WS + ow*2
    int rowoff[MT_PW][2];
    #pragma unroll
    for (int mt = 0; mt < MT_PW; mt++) {
        #pragma unroll
        for (int r = 0; r < 2; r++) {
            int m = (warp * MT_PW + mt) * 16 + g + r * 8;
            if (m >= M) m = M - 1;              // clamped rows computed, never stored
            int oh = m / Wout, ow = m % Wout;
            rowoff[mt][r] = (oh * 2) * WS + ow * 2;
        }
    }

    float acc[MT_PW][2][4];
    #pragma unroll
    for (int mt = 0; mt < MT_PW; mt++)
        #pragma unroll
        for (int nf = 0; nf < 2; nf++)
            #pragma unroll
            for (int r = 0; r < 4; r++) acc[mt][nf][r] = 0.f;

    const float* inp = in + (size_t)n * 16 * Hin * Win;

    #pragma unroll 1
    for (int cg = 0; cg < 8; cg++) {            // 8 groups of 2 ci (K-chunk 32)
        __syncthreads();
        for (int j = t; j < 2 * PLANE; j += NW * 32) {
            int ci_l = j / PLANE, rr = j % PLANE;
            int r = rr / WS, c = rr % WS;
            int gih = r - 1, giw = c - 1;
            float v = 0.f;
            if (gih >= 0 && gih < Hin && giw >= 0 && giw < Win)
                v = inp[((cg * 2 + ci_l) * Hin + gih) * Win + giw];
            sIn[j] = f2tf(v);
        }
        __syncthreads();

        // B fragments for this k-chunk (register-cached, reused across m-tiles)
        unsigned bf[4][2][2];
        #pragma unroll
        for (int kf = 0; kf < 4; kf++)
            #pragma unroll
            for (int nf = 0; nf < 2; nf++) {
                int kb = cg * 32 + kf * 8 + tig;
                bf[kf][nf][0] = Bw[kb * 17 + nf * 8 + g];
                bf[kf][nf][1] = Bw[(kb + 4) * 17 + nf * 8 + g];
            }

        #pragma unroll
        for (int mt = 0; mt < MT_PW; mt++) {
            #pragma unroll
            for (int kf = 0; kf < 4; kf++) {
                unsigned a[4];
                #pragma unroll
                for (int half = 0; half < 2; half++) {
                    int k5 = kf * 8 + tig + half * 4;        // chunk-local k
                    int ci_l = k5 >> 4, tap = k5 & 15;
                    int off = ci_l * PLANE + (tap >> 2) * WS + (tap & 3);
                    a[half * 2 + 0] = sIn[rowoff[mt][0] + off];
                    a[half * 2 + 1] = sIn[rowoff[mt][1] + off];
                }
                #pragma unroll
                for (int nf = 0; nf < 2; nf++)
                    mma_tf32(acc[mt][nf], a[0], a[1], a[2], a[3],
                             bf[kf][nf][0], bf[kf][nf][1]);
            }
        }
    }

    // epilogue: bias + relu, scatter by cout
    #pragma unroll
    for (int mt = 0; mt < MT_PW; mt++) {
        #pragma unroll
        for (int r = 0; r < 2; r++) {
            int m = (warp * MT_PW + mt) * 16 + g + r * 8;
            if (m < M) {
                int oh = m / Wout, ow = m % Wout;
                #pragma unroll
                for (int nf = 0; nf < 2; nf++) {
                    int co = nf * 8 + 2 * tig;
                    float v0 = acc[mt][nf][2 * r + 0] + __ldg(&bias[co]);
                    float v1 = acc[mt][nf][2 * r + 1] + __ldg(&bias[co + 1]);
                    out[((n * 16 + co) * Hout + oh) * Wout + ow] = fmaxf(v0, 0.f);
                    out[((n * 16 + co + 1) * Hout + oh) * Wout + ow] = fmaxf(v1, 0.f);
                }
            }
        }
    }
}

template <int EPI>
__device__ __forceinline__ float epi_apply(float v, int m, int n, int N,
                                           const float* __restrict__ extra) {
    if (EPI == 1) v += extra[(m & 511) * N + n];
    if (EPI == 2) v = v * normcdff(v);
    if (EPI == 3) v += extra[m * N + n];
    return v;
}

// ---------------- GEMM A: 32x64 tile, 256 threads, warp tile 16x16, cp.async ---
template <int EPI>
__global__ void __launch_bounds__(256) gemm32_k(
    const float* __restrict__ A, const float* __restrict__ B,
    const float* __restrict__ bias, const float* __restrict__ extra,
    float* __restrict__ C, int M, int N, int K, int S, int Kc) {
    __shared__ unsigned As[2][32][36];   // raw fp32 bits (HW truncates to tf32)
    __shared__ unsigned Bs[2][32][68];

    const int t = threadIdx.x;
    const int m0 = blockIdx.y * 32, n0 = blockIdx.x * 64;
    const int z = blockIdx.z;
    const int kb0 = z * Kc;
    const int warp = t >> 5, lane = t & 31;
    const int g = lane >> 2, tig = lane & 3;
    const int wm = (warp >> 2) * 16;
    const int wn = (warp & 3) * 16;

    float acc[2][4];
    #pragma unroll
    for (int nf = 0; nf < 2; nf++)
        #pragma unroll
        for (int r = 0; r < 4; r++) acc[nf][r] = 0.f;

    const int a_row = t >> 3, a_col = (t & 7) * 4;
    const int b_row = t >> 4, b_col = (t & 15) * 4;
    const int NC = Kc >> 5;
    const float* Ab = A + kb0 + (size_t)(m0 + a_row) * K + a_col;
    const float* Bb0 = B + (size_t)(kb0 + b_row) * N + n0 + b_col;
    const float* Bb1 = B + (size_t)(kb0 + b_row + 16) * N + n0 + b_col;

    cpasync16(&As[0][a_row][a_col], Ab);
    cpasync16(&Bs[0][b_row][b_col], Bb0);
    cpasync16(&Bs[0][b_row + 16][b_col], Bb1);
    cp_commit();

    for (int c = 0; c < NC; c++) {
        const int s = c & 1;
        if (c + 1 < NC) {
            int k0 = (c + 1) * 32;
            cpasync16(&As[s ^ 1][a_row][a_col], Ab + k0);
            cpasync16(&Bs[s ^ 1][b_row][b_col], Bb0 + (size_t)k0 * N);
            cpasync16(&Bs[s ^ 1][b_row + 16][b_col], Bb1 + (size_t)k0 * N);
        }
        cp_commit();
        cp_wait<1>();
        __syncthreads();

        #pragma unroll
        for (int ks = 0; ks < 4; ks++) {
            int k8 = ks * 8;
            unsigned a0 = As[s][wm + g][k8 + tig];
            unsigned a1 = As[s][wm + g + 8][k8 + tig];
            unsigned a2 = As[s][wm + g][k8 + tig + 4];
            unsigned a3 = As[s][wm + g + 8][k8 + tig + 4];
            #pragma unroll
            for (int nf = 0; nf < 2; nf++) {
                int nc = wn + nf * 8 + g;
                unsigned b0 = Bs[s][k8 + tig][nc];
                unsigned b1 = Bs[s][k8 + tig + 4][nc];
                mma_tf32(acc[nf], a0, a1, a2, a3, b0, b1);
            }
        }
        __syncthreads();
    }

    if (S == 1) {
        #pragma unroll
        for (int half = 0; half < 2; half++) {
            int m = m0 + wm + g + half * 8;
            #pragma unroll
            for (int nf = 0; nf < 2; nf++) {
                int n = n0 + wn + nf * 8 + 2 * tig;
                float v0 = epi_apply<EPI>(acc[nf][2 * half] + bias[n], m, n, N, extra);
                float v1 = epi_apply<EPI>(acc[nf][2 * half + 1] + bias[n + 1], m, n + 1, N, extra);
                *(float2*)&C[m * N + n] = make_float2(v0, v1);
            }
        }
        return;
    }

    float* pz = g_sp + (size_t)z * M * N;
    #pragma unroll
    for (int half = 0; half < 2; half++) {
        int m = m0 + wm + g + half * 8;
        #pragma unroll
        for (int nf = 0; nf < 2; nf++) {
            int n = n0 + wn + nf * 8 + 2 * tig;
            *(float2*)&pz[m * N + n] = make_float2(acc[nf][2 * half], acc[nf][2 * half + 1]);
        }
    }
    __threadfence();
    __syncthreads();
    __shared__ unsigned s_old;
    const int tile = blockIdx.y * gridDim.x + blockIdx.x;
    if (t == 0) s_old = atomicAdd(&g_cnt[tile], 1);
    __syncthreads();
    if (s_old != (unsigned)(S - 1)) return;
    __threadfence();

    #pragma unroll
    for (int half = 0; half < 2; half++) {
        int m = m0 + wm + g + half * 8;
        #pragma unroll
        for (int nf = 0; nf < 2; nf++) {
            int n = n0 + wn + nf * 8 + 2 * tig;
            float v0 = bias[n], v1 = bias[n + 1];
            for (int s2 = 0; s2 < S; s2++) {
                float2 pv = *(const float2*)&g_sp[(size_t)s2 * M * N + m * N + n];
                v0 += pv.x; v1 += pv.y;
            }
            v0 = epi_apply<EPI>(v0, m, n, N, extra);
            v1 = epi_apply<EPI>(v1, m, n + 1, N, extra);
            *(float2*)&C[m * N + n] = make_float2(v0, v1);
        }
    }
    if (t == 0) g_cnt[tile] = 0;
}

// ---------------- GEMM B: 64x64 tile, 256 threads, warp tile 32x16, cp.async ---
template <int EPI>
__global__ void __launch_bounds__(256) gemm64_k(
    const float* __restrict__ A, const float* __restrict__ B,
    const float* __restrict__ bias, const float* __restrict__ extra,
    float* __restrict__ C, int M, int N, int K, int S, int Kc) {
    __shared__ unsigned As[2][64][36];
    __shared__ unsigned Bs[2][32][68];

    const int t = threadIdx.x;
    const int m0 = blockIdx.y * 64, n0 = blockIdx.x * 64;
    const int z = blockIdx.z;
    const int kb0 = z * Kc;
    const int warp = t >> 5, lane = t & 31;
    const int g = lane >> 2, tig = lane & 3;
    const int wm = (warp >> 2) * 32;      // 0 or 32
    const int wn = (warp & 3) * 16;       // 0,16,32,48

    float acc[2][2][4];
    #pragma unroll
    for (int mt = 0; mt < 2; mt++)
        #pragma unroll
        for (int nf = 0; nf < 2; nf++)
            #pragma unroll
            for (int r = 0; r < 4; r++) acc[mt][nf][r] = 0.f;

    const int a_row = t >> 2, a_colb = (t & 3) * 8;
    const int b_row = t >> 3, b_colb = (t & 7) * 8;
    const int NC = Kc >> 5;
    const float* Ab = A + kb0 + (size_t)(m0 + a_row) * K + a_colb;
    const float* Bb = B + (size_t)(kb0 + b_row) * N + n0 + b_colb;

    cpasync16(&As[0][a_row][a_colb], Ab);
    cpasync16(&As[0][a_row][a_colb + 4], Ab + 4);
    cpasync16(&Bs[0][b_row][b_colb], Bb);
    cpasync16(&Bs[0][b_row][b_colb + 4], Bb + 4);
    cp_commit();

    for (int c = 0; c < NC; c++) {
        const int s = c & 1;
        if (c + 1 < NC) {
            int k0 = (c + 1) * 32;
            cpasync16(&As[s ^ 1][a_row][a_colb], Ab + k0);
            cpasync16(&As[s ^ 1][a_row][a_colb + 4], Ab + k0 + 4);
            cpasync16(&Bs[s ^ 1][b_row][b_colb], Bb + (size_t)k0 * N);
            cpasync16(&Bs[s ^ 1][b_row][b_colb + 4], Bb + (size_t)k0 * N + 4);
        }
        cp_commit();
        cp_wait<1>();
        __syncthreads();

        #pragma unroll
        for (int ks = 0; ks < 4; ks++) {
            const int k8 = ks * 8;
            unsigned a[2][4], bf[2][2];
            #pragma unroll
            for (int mt = 0; mt < 2; mt++) {
                int mr = wm + mt * 16 + g;
                a[mt][0] = As[s][mr][k8 + tig];
                a[mt][1] = As[s][mr + 8][k8 + tig];
                a[mt][2] = As[s][mr][k8 + tig + 4];
                a[mt][3] = As[s][mr + 8][k8 + tig + 4];
            }
            #pragma unroll
            for (int nf = 0; nf < 2; nf++) {
                int nc = wn + nf * 8 + g;
                bf[nf][0] = Bs[s][k8 + tig][nc];
                bf[nf][1] = Bs[s][k8 + tig + 4][nc];
            }
            #pragma unroll
            for (int mt = 0; mt < 2; mt++)
                #pragma unroll
                for (int nf = 0; nf < 2; nf++)
                    mma_tf32(acc[mt][nf], a[mt][0], a[mt][1], a[mt][2], a[mt][3],
                             bf[nf][0], bf[nf][1]);
        }
        __syncthreads();
    }

    if (S == 1) {
        #pragma unroll
        for (int mt = 0; mt < 2; mt++)
            #pragma unroll
            for (int half = 0; half < 2; half++) {
                int m = m0 + wm + mt * 16 + g + half * 8;
                #pragma unroll
                for (int nf = 0; nf < 2; nf++) {
                    int n = n0 + wn + nf * 8 + 2 * tig;
                    float v0 = epi_apply<EPI>(acc[mt][nf][2 * half] + bias[n], m, n, N, extra);
                    float v1 = epi_apply<EPI>(acc[mt][nf][2 * half + 1] + bias[n + 1], m, n + 1, N, extra);
                    *(float2*)&C[m * N + n] = make_float2(v0, v1);
                }
            }
        return;
    }

    float* pz = g_sp + (size_t)z * M * N;
    #pragma unroll
    for (int mt = 0; mt < 2; mt++)
        #pragma unroll
        for (int half = 0; half < 2; half++) {
            int m = m0 + wm + mt * 16 + g + half * 8;
            #pragma unroll
            for (int nf = 0; nf < 2; nf++) {
                int n = n0 + wn + nf * 8 + 2 * tig;
                *(float2*)&pz[m * N + n] =
                    make_float2(acc[mt][nf][2 * half], acc[mt][nf][2 * half + 1]);
            }
        }
    __threadfence();
    __syncthreads();
    __shared__ unsigned s_old;
    const int tile = blockIdx.y * gridDim.x + blockIdx.x;
    if (t == 0) s_old = atomicAdd(&g_cnt[tile], 1);
    __syncthreads();
    if (s_old != (unsigned)(S - 1)) return;
    __threadfence();

    #pragma unroll
    for (int mt = 0; mt < 2; mt++)
        #pragma unroll
        for (int half = 0; half < 2; half++) {
            int m = m0 + wm + mt * 16 + g + half * 8;
            #pragma unroll
            for (int nf = 0; nf < 2; nf++) {
                int n = n0 + wn + nf * 8 + 2 * tig;
                float v0 = bias[n], v1 = bias[n + 1];
                for (int s2 = 0; s2 < S; s2++) {
                    float2 pv = *(const float2*)&g_sp[(size_t)s2 * M * N + m * N + n];
                    v0 += pv.x; v1 += pv.y;
                }
                v0 = epi_apply<EPI>(v0, m, n, N, extra);
                v1 = epi_apply<EPI>(v1, m, n + 1, N, extra);
                *(float2*)&C[m * N + n] = make_float2(v0, v1);
            }
        }
    if (t == 0) g_cnt[tile] = 0;
}

// ---------------- layernorm: one warp per row, shuffle reductions ----------------
__global__ void __launch_bounds__(256) ln_k(
    const float* __restrict__ in, const float* __restrict__ gw,
    const float* __restrict__ bw, float* __restrict__ out) {
    const int t = threadIdx.x, warp = t >> 5, lane = t & 31;
    const int row = blockIdx.x * 8 + warp;
    const float4* r = (const float4*)(in + row * 256);
    float4 v0 = r[lane], v1 = r[lane + 32];
    float s = v0.x + v0.y + v0.z + v0.w + v1.x + v1.y + v1.z + v1.w;
    #pragma unroll
    for (int o = 16; o > 0; o >>= 1) s += __shfl_xor_sync(0xffffffffu, s, o);
    float mu = s * (1.f / 256.f);
    float d0x = v0.x - mu, d0y = v0.y - mu, d0z = v0.z - mu, d0w = v0.w - mu;
    float d1x = v1.x - mu, d1y = v1.y - mu, d1z = v1.z - mu, d1w = v1.w - mu;
    float ss = d0x * d0x + d0y * d0y + d0z * d0z + d0w * d0w
             + d1x * d1x + d1y * d1y + d1z * d1z + d1w * d1w;
    #pragma unroll
    for (int o = 16; o > 0; o >>= 1) ss += __shfl_xor_sync(0xffffffffu, ss, o);
    float inv = rsqrtf(ss * (1.f / 256.f) + 1e-5f);
    const float4* g4 = (const float4*)gw;
    const float4* b4 = (const float4*)bw;
    float4 ga = g4[lane], gb = g4[lane + 32];
    float4 ba = b4[lane], bb = b4[lane + 32];
    float4* o4 = (float4*)(out + row * 256);
    o4[lane] = make_float4(d0x * inv * ga.x + ba.x, d0y * inv * ga.y + ba.y,
                           d0z * inv * ga.z + ba.z, d0w * inv * ga.w + ba.w);
    o4[lane + 32] = make_float4(d1x * inv * gb.x + bb.x, d1y * inv * gb.y + bb.y,
                                d1z * inv * gb.z + bb.z, d1w * inv * gb.w + bb.w);
}

// ---------------- causal attention: 2 threads per query (d-split) ----------------
__global__ void __launch_bounds__(128) attn_k(const float* __restrict__ c,
                                              float* __restrict__ x) {
    __shared__ float Ks[32][32];
    __shared__ float Vs[32][32];
    const int t = threadIdx.x;            // 128 threads
    const int qt = blockIdx.x;            // 8 query tiles of 64
    const int bh = blockIdx.y;            // 16 (b,h)
    const int b = bh >> 3, h = bh & 7;
    const int qi = qt * 64 + (t & 63);
    const int dhalf = t >> 6;             // 0 or 1: V dims [dhalf*16, +16)
    const float* crow = c + (b * 512 + qi) * 768 + h * 32;

    const float SC = 0.17677669529663687f;  // 1/sqrt(32)
    float q[32];
    #pragma unroll
    for (int d4 = 0; d4 < 8; d4++) {
        float4 qv = *(const float4*)(crow + d4 * 4);
        q[4 * d4 + 0] = qv.x * SC;
        q[4 * d4 + 1] = qv.y * SC;
        q[4 * d4 + 2] = qv.z * SC;
        q[4 * d4 + 3] = qv.w * SC;
    }
    float acc[16];
    #pragma unroll
    for (int d = 0; d < 16; d++) acc[d] = 0.f;
    float mrun = -1e30f, l = 0.f;

    const int kend = qt * 64 + 63;
    const int jj = t >> 2, q8 = (t & 3) * 8;
    for (int kb = 0; kb <= kend; kb += 32) {
        const float* kr = c + (b * 512 + kb + jj) * 768 + 256 + h * 32 + q8;
        *(float4*)&Ks[jj][q8]     = *(const float4*)(kr);
        *(float4*)&Ks[jj][q8 + 4] = *(const float4*)(kr + 4);
        *(float4*)&Vs[jj][q8]     = *(const float4*)(kr + 256);
        *(float4*)&Vs[jj][q8 + 4] = *(const float4*)(kr + 260);
        __syncthreads();
        if (kb <= qi) {
            int jmax = qi - kb;
            if (jmax > 31) jmax = 31;
            float sarr[32];
            float tmax = -1e30f;
            #pragma unroll
            for (int j = 0; j < 32; j++) {
                if (j <= jmax) {
                    float s = 0.f;
                    #pragma unroll
                    for (int d = 0; d < 32; d++) s += q[d] * Ks[j][d];
                    sarr[j] = s;
                    tmax = fmaxf(tmax, s);
                }
            }
            float newm = fmaxf(mrun, tmax);
            float alpha = __expf(mrun - newm);
            l *= alpha;
            #pragma unroll
            for (int d = 0; d < 16; d++) acc[d] *= alpha;
            #pragma unroll
            for (int j = 0; j < 32; j++) {
                if (j <= jmax) {
                    float p = __expf(sarr[j] - newm);
                    l += p;
                    #pragma unroll
                    for (int d = 0; d < 16; d++) acc[d] += p * Vs[j][dhalf * 16 + d];
                }
            }
            mrun = newm;
        }
        __syncthreads();
    }
    float inv = 1.f / l;
    float* xr = x + (b * 512 + qi) * 256 + h * 32 + dhalf * 16;
    #pragma unroll
    for (int d = 0; d < 16; d++) xr[d] += acc[d] * inv;
}

// ---------------- deterministic global mean/std (ddof=1) + normalize ------------
__global__ void reduce_k(const float* __restrict__ e) {
    __shared__ double s1[256], s2[256];
    const int t = threadIdx.x;
    double s = 0.0, ss = 0.0;
    for (int i = blockIdx.x * 256 + t; i < 262144; i += 256 * 256) {
        double v = (double)e[i];
        s += v;
        ss += v * v;
    }
    s1[t] = s;
    s2[t] = ss;
    __syncthreads();
    for (int k = 128; k > 0; k >>= 1) {
        if (t < k) { s1[t] += s1[t + k]; s2[t] += s2[t + k]; }
        __syncthreads();
    }
    if (t == 0) { g_part[blockIdx.x] = s1[0]; g_part[256 + blockIdx.x] = s2[0]; }
}

__global__ void norm_k(float* e) {
    __shared__ double s1[256], s2[256];
    const int t = threadIdx.x;
    s1[t] = g_part[t];
    s2[t] = g_part[256 + t];
    __syncthreads();
    for (int k = 128; k > 0; k >>= 1) {
        if (t < k) { s1[t] += s1[t + k]; s2[t] += s2[t + k]; }
        __syncthreads();
    }
    const double n = 262144.0;
    double mu = s1[0] / n;
    double var = (s2[0] - n * mu * mu) / (n - 1.0);
    float inv = (float)(1.0 / sqrt(var));
    float fmu = (float)mu;
    int i = (blockIdx.x * 256 + t) * 4;
    float4 v = *(float4*)&e[i];
    v.x = (v.x - fmu) * inv + 1e-10f;
    v.y = (v.y - fmu) * inv + 1e-10f;
    v.z = (v.z - fmu) * inv + 1e-10f;
    v.w = (v.w - fmu) * inv + 1e-10f;
    *(float4*)&e[i] = v;
}

// ---------------- launch ----------------
extern "C" void kernel_launch(void* const* d_in, const int* in_sizes, int n_in,
                              void* d_out, int out_size) {
    const float* state   = (const float*)d_in[0];
    const float* conv_w1 = (const float*)d_in[1];
    const float* conv_b1 = (const float*)d_in[2];
    const float* conv_w2 = (const float*)d_in[3];
    const float* conv_b2 = (const float*)d_in[4];
    const float* conv_w3 = (const float*)d_in[5];
    const float* conv_b3 = (const float*)d_in[6];
    const float* pre_w   = (const float*)d_in[7];
    const float* pre_b   = (const float*)d_in[8];
    const float* pos_w   = (const float*)d_in[9];
    const float* ln1_g   = (const float*)d_in[10];
    const float* ln1_b   = (const float*)d_in[11];
    const float* enc_w   = (const float*)d_in[12];
    const float* enc_b   = (const float*)d_in[13];
    const float* ln2_g   = (const float*)d_in[14];
    const float* ln2_b   = (const float*)d_in[15];
    const float* ffn_w1  = (const float*)d_in[16];
    const float* ffn_b1  = (const float*)d_in[17];
    const float* ffn_w2  = (const float*)d_in[18];
    const float* ffn_b2  = (const float*)d_in[19];
    const float* emb_w   = (const float*)d_in[20];
    const float* emb_b   = (const float*)d_in[21];
    float* out = (float*)d_out;

    float *x1, *x2, *x3, *x, *xn, *cb, *hb;
    cudaGetSymbolAddress((void**)&x1, g_x1);
    cudaGetSymbolAddress((void**)&x2, g_x2);
    cudaGetSymbolAddress((void**)&x3, g_x3);
    cudaGetSymbolAddress((void**)&x,  g_x);
    cudaGetSymbolAddress((void**)&xn, g_xn);
    cudaGetSymbolAddress((void**)&cb, g_c);
    cudaGetSymbolAddress((void**)&hb, g_h);

    // conv stem: conv1 fp32; conv2/conv3 tensorized implicit GEMM
    conv_k<3><<<2880, 256>>>(state, conv_w1, conv_b1, x1, 96, 120, 48, 60);
    convt_k<48, 60, 24, 30, 8><<<1024, 256>>>(x1, conv_w2, conv_b2, x2);
    convt_k<24, 30, 12, 15, 4><<<1024, 128>>>(x2, conv_w3, conv_b3, x3);

    // pre-projection + positional  (64x64 tiles, S=9, cp.async)
    gemm64_k<1><<<dim3(4, 16, 9), 256>>>(x3, pre_w, pre_b, pos_w, x,
                                         1024, 256, 2880, 9, 320);

    for (int k = 0; k < 4; k++) {
        ln_k<<<128, 256>>>(x, ln1_g + k * 256, ln1_b + k * 256, xn);
        gemm32_k<0><<<dim3(12, 32, 2), 256>>>(xn, enc_w + k * 256 * 768, enc_b + k * 768,
                                              nullptr, cb, 1024, 768, 256, 2, 128);
        attn_k<<<dim3(8, 16), 128>>>(cb, x);
        ln_k<<<128, 256>>>(x, ln2_g + k * 256, ln2_b + k * 256, x);
        gemm32_k<2><<<dim3(16, 32, 2), 256>>>(x, ffn_w1 + k * 256 * 1024, ffn_b1 + k * 1024,
                                              nullptr, hb, 1024, 1024, 256, 2, 128);
        gemm32_k<3><<<dim3(4, 32, 4), 256>>>(hb, ffn_w2 + k * 1024 * 256, ffn_b2 + k * 256,
                                             x, x, 1024, 256, 1024, 4, 256);
    }

    gemm32_k<0><<<dim3(4, 32, 4), 256>>>(x, emb_w, emb_b, nullptr, out,
                                         1024, 256, 256, 4, 64);

    reduce_k<<<256, 256>>>(out);
    norm_k<<<256, 256>>>(out);
}

// round 14
// speedup vs baseline: 1.0119x; 1.0119x over previous
#include <cuda_runtime.h>
#include <math.h>

// ---------------- scratch (device globals; no allocation allowed) ----------------
__device__ float g_x1[1024 * 16 * 48 * 60];   // conv1 out
__device__ float g_x2[1024 * 16 * 24 * 30];   // conv2 out
__device__ float g_x3[1024 * 16 * 12 * 15];   // conv3 out (= tokens x 2880)
__device__ float g_x [1024 * 256];            // residual stream
__device__ float g_xn[1024 * 256];            // ln1 output
__device__ float g_c [1024 * 768];            // qkv
__device__ float g_h [1024 * 1024];           // ffn hidden
__device__ float g_sp[4 * 1024 * 1024];       // split-K partials
__device__ unsigned g_cnt[512];               // per-tile arrival counters
__device__ double g_part[512];                // partial sums / sumsq

// ---------------- helpers ----------------
__device__ __forceinline__ unsigned f2tf(float f) {
    unsigned u;
    asm("cvt.rna.tf32.f32 %0, %1;" : "=r"(u) : "f"(f));
    return u;
}
__device__ __forceinline__ void mma_tf32(float c[4], unsigned a0, unsigned a1,
                                         unsigned a2, unsigned a3,
                                         unsigned b0, unsigned b1) {
    asm volatile(
        "mma.sync.aligned.m16n8k8.row.col.f32.tf32.tf32.f32 "
        "{%0,%1,%2,%3}, {%4,%5,%6,%7}, {%8,%9}, {%0,%1,%2,%3};\n"
        : "+f"(c[0]), "+f"(c[1]), "+f"(c[2]), "+f"(c[3])
        : "r"(a0), "r"(a1), "r"(a2), "r"(a3), "r"(b0), "r"(b1));
}
__device__ __forceinline__ void cpasync16(const void* smem_dst, const void* gsrc) {
    unsigned s = (unsigned)__cvta_generic_to_shared(smem_dst);
    asm volatile("cp.async.cg.shared.global [%0], [%1], 16;" :: "r"(s), "l"(gsrc));
}
__device__ __forceinline__ void cp_commit() {
    asm volatile("cp.async.commit_group;");
}
template <int N>
__device__ __forceinline__ void cp_wait() {
    asm volatile("cp.async.wait_group %0;" :: "n"(N));
}

// ---------------- conv1 tensorized: CIN=3, 96x120 -> 48x60, strip of 4 out rows --
// Implicit GEMM per strip: M=240 pixels, N=16 couts, K=48 (3ci x 16 taps).
// Halo strip plane (10 x 122 per ci) staged once (tf32-RNA); weights [k][co].
__global__ void __launch_bounds__(256) conv1t_k(
    const float* __restrict__ in, const float* __restrict__ w,
    const float* __restrict__ bias, float* __restrict__ out) {
    constexpr int WS = 122, RS = 10, PLANE = RS * WS;   // halo strip plane
    constexpr int M = 240;                              // 4 out rows x 60
    __shared__ unsigned sIn[3 * PLANE];                 // 3 ci planes (tf32 bits)
    __shared__ unsigned Bw[48 * 17];                    // weights [k][co]

    const int strip = blockIdx.x;        // 0..11
    const int n = blockIdx.y;            // image
    const int t = threadIdx.x;
    const int warp = t >> 5, lane = t & 31;
    const int g = lane >> 2, tig = lane & 3;

    // stage weights: w layout [co][ci][kh][kw] = co*48 + k
    for (int i = t; i < 48 * 16; i += 256) {
        int co = i / 48, k = i % 48;
        Bw[k * 17 + co] = f2tf(w[i]);
    }

    // stage input halo strip: global ih = strip*8 + r - 1, giw = c - 1
    const float* inp = in + (size_t)n * 3 * 96 * 120;
    for (int j = t; j < 3 * PLANE; j += 256) {
        int ci = j / PLANE, rr = j % PLANE;
        int r = rr / WS, c = rr % WS;
        int gih = strip * 8 + r - 1, giw = c - 1;
        float v = 0.f;
        if (gih >= 0 && gih < 96 && giw >= 0 && giw < 120)
            v = inp[(ci * 96 + gih) * 120 + giw];
        sIn[j] = f2tf(v);
    }
    __syncthreads();

    // B fragments (register-cached): 6 k-steps of 8
    unsigned bf[6][2][2];
    #pragma unroll
    for (int kf = 0; kf < 6; kf++)
        #pragma unroll
        for (int nf = 0; nf < 2; nf++) {
            int kb = kf * 8 + tig;
            bf[kf][nf][0] = Bw[kb * 17 + nf * 8 + g];
            bf[kf][nf][1] = Bw[(kb + 4) * 17 + nf * 8 + g];
        }

    // 2 m-tiles per warp (15 real tiles + 1 clamped)
    float acc[2][2][4];
    #pragma unroll
    for (int mt = 0; mt < 2; mt++)
        #pragma unroll
        for (int nf = 0; nf < 2; nf++)
            #pragma unroll
            for (int r = 0; r < 4; r++) acc[mt][nf][r] = 0.f;

    int rowoff[2][2];
    #pragma unroll
    for (int mt = 0; mt < 2; mt++)
        #pragma unroll
        for (int r = 0; r < 2; r++) {
            int m = (warp * 2 + mt) * 16 + g + r * 8;
            if (m >= M) m = M - 1;
            int ohl = m / 60, ow = m % 60;
            rowoff[mt][r] = (ohl * 2) * WS + ow * 2;
        }

    #pragma unroll
    for (int mt = 0; mt < 2; mt++) {
        #pragma unroll
        for (int kf = 0; kf < 6; kf++) {
            unsigned a[4];
            #pragma unroll
            for (int half = 0; half < 2; half++) {
                int k5 = kf * 8 + tig + half * 4;
                int ci = k5 >> 4, tap = k5 & 15;
                int off = ci * PLANE + (tap >> 2) * WS + (tap & 3);
                a[half * 2 + 0] = sIn[rowoff[mt][0] + off];
                a[half * 2 + 1] = sIn[rowoff[mt][1] + off];
            }
            #pragma unroll
            for (int nf = 0; nf < 2; nf++)
                mma_tf32(acc[mt][nf], a[0], a[1], a[2], a[3],
                         bf[kf][nf][0], bf[kf][nf][1]);
        }
    }

    #pragma unroll
    for (int mt = 0; mt < 2; mt++)
        #pragma unroll
        for (int r = 0; r < 2; r++) {
            int m = (warp * 2 + mt) * 16 + g + r * 8;
            if (m < M) {
                int oh = strip * 4 + m / 60, ow = m % 60;
                #pragma unroll
                for (int nf = 0; nf < 2; nf++) {
                    int co = nf * 8 + 2 * tig;
                    float v0 = acc[mt][nf][2 * r + 0] + __ldg(&bias[co]);
                    float v1 = acc[mt][nf][2 * r + 1] + __ldg(&bias[co + 1]);
                    out[((n * 16 + co) * 48 + oh) * 60 + ow] = fmaxf(v0, 0.f);
                    out[((n * 16 + co + 1) * 48 + oh) * 60 + ow] = fmaxf(v1, 0.f);
                }
            }
        }
}

// ---------------- tensorized conv (CIN=16, COUT=16, 4x4, stride2, pad1) --------
template <int Hin, int Win, int Hout, int Wout, int NW>
__global__ void __launch_bounds__(NW * 32) convt_k(
    const float* __restrict__ in, const float* __restrict__ w,
    const float* __restrict__ bias, float* __restrict__ out) {
    constexpr int HS = Hin + 2, WS = Win + 2;
    constexpr int PLANE = HS * WS;
    constexpr int M = Hout * Wout;
    constexpr int MT_TOT = (M + 15) / 16;
    constexpr int MT_PW = (MT_TOT + NW - 1) / NW;

    __shared__ unsigned sIn[2 * PLANE];     // 2 halo planes, tf32 bits
    __shared__ unsigned Bw[256 * 17];       // weights: [k][co], stride 17

    const int n = blockIdx.x;
    const int t = threadIdx.x;
    const int warp = t >> 5, lane = t & 31;
    const int g = lane >> 2, tig = lane & 3;

    for (int i = t; i < 256 * 16; i += NW * 32) {
        int co = i >> 8, k = i & 255;
        Bw[k * 17 + co] = f2tf(w[i]);
    }

    int rowoff[MT_PW][2];
    #pragma unroll
    for (int mt = 0; mt < MT_PW; mt++) {
        #pragma unroll
        for (int r = 0; r < 2; r++) {
            int m = (warp * MT_PW + mt) * 16 + g + r * 8;
            if (m >= M) m = M - 1;
            int oh = m / Wout, ow = m % Wout;
            rowoff[mt][r] = (oh * 2) * WS + ow * 2;
        }
    }

    float acc[MT_PW][2][4];
    #pragma unroll
    for (int mt = 0; mt < MT_PW; mt++)
        #pragma unroll
        for (int nf = 0; nf < 2; nf++)
            #pragma unroll
            for (int r = 0; r < 4; r++) acc[mt][nf][r] = 0.f;

    const float* inp = in + (size_t)n * 16 * Hin * Win;

    #pragma unroll 1
    for (int cg = 0; cg < 8; cg++) {
        __syncthreads();
        for (int j = t; j < 2 * PLANE; j += NW * 32) {
            int ci_l = j / PLANE, rr = j % PLANE;
            int r = rr / WS, c = rr % WS;
            int gih = r - 1, giw = c - 1;
            float v = 0.f;
            if (gih >= 0 && gih < Hin && giw >= 0 && giw < Win)
                v = inp[((cg * 2 + ci_l) * Hin + gih) * Win + giw];
            sIn[j] = f2tf(v);
        }
        __syncthreads();

        unsigned bf[4][2][2];
        #pragma unroll
        for (int kf = 0; kf < 4; kf++)
            #pragma unroll
            for (int nf = 0; nf < 2; nf++) {
                int kb = cg * 32 + kf * 8 + tig;
                bf[kf][nf][0] = Bw[kb * 17 + nf * 8 + g];
                bf[kf][nf][1] = Bw[(kb + 4) * 17 + nf * 8 + g];
            }

        #pragma unroll
        for (int mt = 0; mt < MT_PW; mt++) {
            #pragma unroll
            for (int kf = 0; kf < 4; kf++) {
                unsigned a[4];
                #pragma unroll
                for (int half = 0; half < 2; half++) {
                    int k5 = kf * 8 + tig + half * 4;
                    int ci_l = k5 >> 4, tap = k5 & 15;
                    int off = ci_l * PLANE + (tap >> 2) * WS + (tap & 3);
                    a[half * 2 + 0] = sIn[rowoff[mt][0] + off];
                    a[half * 2 + 1] = sIn[rowoff[mt][1] + off];
                }
                #pragma unroll
                for (int nf = 0; nf < 2; nf++)
                    mma_tf32(acc[mt][nf], a[0], a[1], a[2], a[3],
                             bf[kf][nf][0], bf[kf][nf][1]);
            }
        }
    }

    #pragma unroll
    for (int mt = 0; mt < MT_PW; mt++) {
        #pragma unroll
        for (int r = 0; r < 2; r++) {
            int m = (warp * MT_PW + mt) * 16 + g + r * 8;
            if (m < M) {
                int oh = m / Wout, ow = m % Wout;
                #pragma unroll
                for (int nf = 0; nf < 2; nf++) {
                    int co = nf * 8 + 2 * tig;
                    float v0 = acc[mt][nf][2 * r + 0] + __ldg(&bias[co]);
                    float v1 = acc[mt][nf][2 * r + 1] + __ldg(&bias[co + 1]);
                    out[((n * 16 + co) * Hout + oh) * Wout + ow] = fmaxf(v0, 0.f);
                    out[((n * 16 + co + 1) * Hout + oh) * Wout + ow] = fmaxf(v1, 0.f);
                }
            }
        }
    }
}

template <int EPI>
__device__ __forceinline__ float epi_apply(float v, int m, int n, int N,
                                           const float* __restrict__ extra) {
    if (EPI == 1) v += extra[(m & 511) * N + n];
    if (EPI == 2) v = v * normcdff(v);
    if (EPI == 3) v += extra[m * N + n];
    return v;
}

// ---------------- GEMM A: 32x64 tile, 256 threads, warp tile 16x16, cp.async ---
template <int EPI>
__global__ void __launch_bounds__(256) gemm32_k(
    const float* __restrict__ A, const float* __restrict__ B,
    const float* __restrict__ bias, const float* __restrict__ extra,
    float* __restrict__ C, int M, int N, int K, int S, int Kc) {
    __shared__ unsigned As[2][32][36];
    __shared__ unsigned Bs[2][32][68];

    const int t = threadIdx.x;
    const int m0 = blockIdx.y * 32, n0 = blockIdx.x * 64;
    const int z = blockIdx.z;
    const int kb0 = z * Kc;
    const int warp = t >> 5, lane = t & 31;
    const int g = lane >> 2, tig = lane & 3;
    const int wm = (warp >> 2) * 16;
    const int wn = (warp & 3) * 16;

    float acc[2][4];
    #pragma unroll
    for (int nf = 0; nf < 2; nf++)
        #pragma unroll
        for (int r = 0; r < 4; r++) acc[nf][r] = 0.f;

    const int a_row = t >> 3, a_col = (t & 7) * 4;
    const int b_row = t >> 4, b_col = (t & 15) * 4;
    const int NC = Kc >> 5;
    const float* Ab = A + kb0 + (size_t)(m0 + a_row) * K + a_col;
    const float* Bb0 = B + (size_t)(kb0 + b_row) * N + n0 + b_col;
    const float* Bb1 = B + (size_t)(kb0 + b_row + 16) * N + n0 + b_col;

    cpasync16(&As[0][a_row][a_col], Ab);
    cpasync16(&Bs[0][b_row][b_col], Bb0);
    cpasync16(&Bs[0][b_row + 16][b_col], Bb1);
    cp_commit();

    for (int c = 0; c < NC; c++) {
        const int s = c & 1;
        if (c + 1 < NC) {
            int k0 = (c + 1) * 32;
            cpasync16(&As[s ^ 1][a_row][a_col], Ab + k0);
            cpasync16(&Bs[s ^ 1][b_row][b_col], Bb0 + (size_t)k0 * N);
            cpasync16(&Bs[s ^ 1][b_row + 16][b_col], Bb1 + (size_t)k0 * N);
        }
        cp_commit();
        cp_wait<1>();
        __syncthreads();

        #pragma unroll
        for (int ks = 0; ks < 4; ks++) {
            int k8 = ks * 8;
            unsigned a0 = As[s][wm + g][k8 + tig];
            unsigned a1 = As[s][wm + g + 8][k8 + tig];
            unsigned a2 = As[s][wm + g][k8 + tig + 4];
            unsigned a3 = As[s][wm + g + 8][k8 + tig + 4];
            #pragma unroll
            for (int nf = 0; nf < 2; nf++) {
                int nc = wn + nf * 8 + g;
                unsigned b0 = Bs[s][k8 + tig][nc];
                unsigned b1 = Bs[s][k8 + tig + 4][nc];
                mma_tf32(acc[nf], a0, a1, a2, a3, b0, b1);
            }
        }
        __syncthreads();
    }

    if (S == 1) {
        #pragma unroll
        for (int half = 0; half < 2; half++) {
            int m = m0 + wm + g + half * 8;
            #pragma unroll
            for (int nf = 0; nf < 2; nf++) {
                int n = n0 + wn + nf * 8 + 2 * tig;
                float v0 = epi_apply<EPI>(acc[nf][2 * half] + bias[n], m, n, N, extra);
                float v1 = epi_apply<EPI>(acc[nf][2 * half + 1] + bias[n + 1], m, n + 1, N, extra);
                *(float2*)&C[m * N + n] = make_float2(v0, v1);
            }
        }
        return;
    }

    float* pz = g_sp + (size_t)z * M * N;
    #pragma unroll
    for (int half = 0; half < 2; half++) {
        int m = m0 + wm + g + half * 8;
        #pragma unroll
        for (int nf = 0; nf < 2; nf++) {
            int n = n0 + wn + nf * 8 + 2 * tig;
            *(float2*)&pz[m * N + n] = make_float2(acc[nf][2 * half], acc[nf][2 * half + 1]);
        }
    }
    __threadfence();
    __syncthreads();
    __shared__ unsigned s_old;
    const int tile = blockIdx.y * gridDim.x + blockIdx.x;
    if (t == 0) s_old = atomicAdd(&g_cnt[tile], 1);
    __syncthreads();
    if (s_old != (unsigned)(S - 1)) return;
    __threadfence();

    #pragma unroll
    for (int half = 0; half < 2; half++) {
        int m = m0 + wm + g + half * 8;
        #pragma unroll
        for (int nf = 0; nf < 2; nf++) {
            int n = n0 + wn + nf * 8 + 2 * tig;
            float v0 = bias[n], v1 = bias[n + 1];
            for (int s2 = 0; s2 < S; s2++) {
                float2 pv = *(const float2*)&g_sp[(size_t)s2 * M * N + m * N + n];
                v0 += pv.x; v1 += pv.y;
            }
            v0 = epi_apply<EPI>(v0, m, n, N, extra);
            v1 = epi_apply<EPI>(v1, m, n + 1, N, extra);
            *(float2*)&C[m * N + n] = make_float2(v0, v1);
        }
    }
    if (t == 0) g_cnt[tile] = 0;
}

// ---------------- GEMM B: 64x64 tile, 256 threads, warp tile 32x16, cp.async ---
template <int EPI>
__global__ void __launch_bounds__(256) gemm64_k(
    const float* __restrict__ A, const float* __restrict__ B,
    const float* __restrict__ bias, const float* __restrict__ extra,
    float* __restrict__ C, int M, int N, int K, int S, int Kc) {
    __shared__ unsigned As[2][64][36];
    __shared__ unsigned Bs[2][32][68];

    const int t = threadIdx.x;
    const int m0 = blockIdx.y * 64, n0 = blockIdx.x * 64;
    const int z = blockIdx.z;
    const int kb0 = z * Kc;
    const int warp = t >> 5, lane = t & 31;
    const int g = lane >> 2, tig = lane & 3;
    const int wm = (warp >> 2) * 32;
    const int wn = (warp & 3) * 16;

    float acc[2][2][4];
    #pragma unroll
    for (int mt = 0; mt < 2; mt++)
        #pragma unroll
        for (int nf = 0; nf < 2; nf++)
            #pragma unroll
            for (int r = 0; r < 4; r++) acc[mt][nf][r] = 0.f;

    const int a_row = t >> 2, a_colb = (t & 3) * 8;
    const int b_row = t >> 3, b_colb = (t & 7) * 8;
    const int NC = Kc >> 5;
    const float* Ab = A + kb0 + (size_t)(m0 + a_row) * K + a_colb;
    const float* Bb = B + (size_t)(kb0 + b_row) * N + n0 + b_colb;

    cpasync16(&As[0][a_row][a_colb], Ab);
    cpasync16(&As[0][a_row][a_colb + 4], Ab + 4);
    cpasync16(&Bs[0][b_row][b_colb], Bb);
    cpasync16(&Bs[0][b_row][b_colb + 4], Bb + 4);
    cp_commit();

    for (int c = 0; c < NC; c++) {
        const int s = c & 1;
        if (c + 1 < NC) {
            int k0 = (c + 1) * 32;
            cpasync16(&As[s ^ 1][a_row][a_colb], Ab + k0);
            cpasync16(&As[s ^ 1][a_row][a_colb + 4], Ab + k0 + 4);
            cpasync16(&Bs[s ^ 1][b_row][b_colb], Bb + (size_t)k0 * N);
            cpasync16(&Bs[s ^ 1][b_row][b_colb + 4], Bb + (size_t)k0 * N + 4);
        }
        cp_commit();
        cp_wait<1>();
        __syncthreads();

        #pragma unroll
        for (int ks = 0; ks < 4; ks++) {
            const int k8 = ks * 8;
            unsigned a[2][4], bf[2][2];
            #pragma unroll
            for (int mt = 0; mt < 2; mt++) {
                int mr = wm + mt * 16 + g;
                a[mt][0] = As[s][mr][k8 + tig];
                a[mt][1] = As[s][mr + 8][k8 + tig];
                a[mt][2] = As[s][mr][k8 + tig + 4];
                a[mt][3] = As[s][mr + 8][k8 + tig + 4];
            }
            #pragma unroll
            for (int nf = 0; nf < 2; nf++) {
                int nc = wn + nf * 8 + g;
                bf[nf][0] = Bs[s][k8 + tig][nc];
                bf[nf][1] = Bs[s][k8 + tig + 4][nc];
            }
            #pragma unroll
            for (int mt = 0; mt < 2; mt++)
                #pragma unroll
                for (int nf = 0; nf < 2; nf++)
                    mma_tf32(acc[mt][nf], a[mt][0], a[mt][1], a[mt][2], a[mt][3],
                             bf[nf][0], bf[nf][1]);
        }
        __syncthreads();
    }

    if (S == 1) {
        #pragma unroll
        for (int mt = 0; mt < 2; mt++)
            #pragma unroll
            for (int half = 0; half < 2; half++) {
                int m = m0 + wm + mt * 16 + g + half * 8;
                #pragma unroll
                for (int nf = 0; nf < 2; nf++) {
                    int n = n0 + wn + nf * 8 + 2 * tig;
                    float v0 = epi_apply<EPI>(acc[mt][nf][2 * half] + bias[n], m, n, N, extra);
                    float v1 = epi_apply<EPI>(acc[mt][nf][2 * half + 1] + bias[n + 1], m, n + 1, N, extra);
                    *(float2*)&C[m * N + n] = make_float2(v0, v1);
                }
            }
        return;
    }

    float* pz = g_sp + (size_t)z * M * N;
    #pragma unroll
    for (int mt = 0; mt < 2; mt++)
        #pragma unroll
        for (int half = 0; half < 2; half++) {
            int m = m0 + wm + mt * 16 + g + half * 8;
            #pragma unroll
            for (int nf = 0; nf < 2; nf++) {
                int n = n0 + wn + nf * 8 + 2 * tig;
                *(float2*)&pz[m * N + n] =
                    make_float2(acc[mt][nf][2 * half], acc[mt][nf][2 * half + 1]);
            }
        }
    __threadfence();
    __syncthreads();
    __shared__ unsigned s_old;
    const int tile = blockIdx.y * gridDim.x + blockIdx.x;
    if (t == 0) s_old = atomicAdd(&g_cnt[tile], 1);
    __syncthreads();
    if (s_old != (unsigned)(S - 1)) return;
    __threadfence();

    #pragma unroll
    for (int mt = 0; mt < 2; mt++)
        #pragma unroll
        for (int half = 0; half < 2; half++) {
            int m = m0 + wm + mt * 16 + g + half * 8;
            #pragma unroll
            for (int nf = 0; nf < 2; nf++) {
                int n = n0 + wn + nf * 8 + 2 * tig;
                float v0 = bias[n], v1 = bias[n + 1];
                for (int s2 = 0; s2 < S; s2++) {
                    float2 pv = *(const float2*)&g_sp[(size_t)s2 * M * N + m * N + n];
                    v0 += pv.x; v1 += pv.y;
                }
                v0 = epi_apply<EPI>(v0, m, n, N, extra);
                v1 = epi_apply<EPI>(v1, m, n + 1, N, extra);
                *(float2*)&C[m * N + n] = make_float2(v0, v1);
            }
        }
    if (t == 0) g_cnt[tile] = 0;
}

// ---------------- layernorm: one warp per row, shuffle reductions ----------------
__global__ void __launch_bounds__(256) ln_k(
    const float* __restrict__ in, const float* __restrict__ gw,
    const float* __restrict__ bw, float* __restrict__ out) {
    const int t = threadIdx.x, warp = t >> 5, lane = t & 31;
    const int row = blockIdx.x * 8 + warp;
    const float4* r = (const float4*)(in + row * 256);
    float4 v0 = r[lane], v1 = r[lane + 32];
    float s = v0.x + v0.y + v0.z + v0.w + v1.x + v1.y + v1.z + v1.w;
    #pragma unroll
    for (int o = 16; o > 0; o >>= 1) s += __shfl_xor_sync(0xffffffffu, s, o);
    float mu = s * (1.f / 256.f);
    float d0x = v0.x - mu, d0y = v0.y - mu, d0z = v0.z - mu, d0w = v0.w - mu;
    float d1x = v1.x - mu, d1y = v1.y - mu, d1z = v1.z - mu, d1w = v1.w - mu;
    float ss = d0x * d0x + d0y * d0y + d0z * d0z + d0w * d0w
             + d1x * d1x + d1y * d1y + d1z * d1z + d1w * d1w;
    #pragma unroll
    for (int o = 16; o > 0; o >>= 1) ss += __shfl_xor_sync(0xffffffffu, ss, o);
    float inv = rsqrtf(ss * (1.f / 256.f) + 1e-5f);
    const float4* g4 = (const float4*)gw;
    const float4* b4 = (const float4*)bw;
    float4 ga = g4[lane], gb = g4[lane + 32];
    float4 ba = b4[lane], bb = b4[lane + 32];
    float4* o4 = (float4*)(out + row * 256);
    o4[lane] = make_float4(d0x * inv * ga.x + ba.x, d0y * inv * ga.y + ba.y,
                           d0z * inv * ga.z + ba.z, d0w * inv * ga.w + ba.w);
    o4[lane + 32] = make_float4(d1x * inv * gb.x + bb.x, d1y * inv * gb.y + bb.y,
                                d1z * inv * gb.z + bb.z, d1w * inv * gb.w + bb.w);
}

// ---------------- causal attention: 2 threads per query (d-split) ----------------
__global__ void __launch_bounds__(128) attn_k(const float* __restrict__ c,
                                              float* __restrict__ x) {
    __shared__ float Ks[32][32];
    __shared__ float Vs[32][32];
    const int t = threadIdx.x;
    const int qt = blockIdx.x;
    const int bh = blockIdx.y;
    const int b = bh >> 3, h = bh & 7;
    const int qi = qt * 64 + (t & 63);
    const int dhalf = t >> 6;
    const float* crow = c + (b * 512 + qi) * 768 + h * 32;

    const float SC = 0.17677669529663687f;
    float q[32];
    #pragma unroll
    for (int d4 = 0; d4 < 8; d4++) {
        float4 qv = *(const float4*)(crow + d4 * 4);
        q[4 * d4 + 0] = qv.x * SC;
        q[4 * d4 + 1] = qv.y * SC;
        q[4 * d4 + 2] = qv.z * SC;
        q[4 * d4 + 3] = qv.w * SC;
    }
    float acc[16];
    #pragma unroll
    for (int d = 0; d < 16; d++) acc[d] = 0.f;
    float mrun = -1e30f, l = 0.f;

    const int kend = qt * 64 + 63;
    const int jj = t >> 2, q8 = (t & 3) * 8;
    for (int kb = 0; kb <= kend; kb += 32) {
        const float* kr = c + (b * 512 + kb + jj) * 768 + 256 + h * 32 + q8;
        *(float4*)&Ks[jj][q8]     = *(const float4*)(kr);
        *(float4*)&Ks[jj][q8 + 4] = *(const float4*)(kr + 4);
        *(float4*)&Vs[jj][q8]     = *(const float4*)(kr + 256);
        *(float4*)&Vs[jj][q8 + 4] = *(const float4*)(kr + 260);
        __syncthreads();
        if (kb <= qi) {
            int jmax = qi - kb;
            if (jmax > 31) jmax = 31;
            float sarr[32];
            float tmax = -1e30f;
            #pragma unroll
            for (int j = 0; j < 32; j++) {
                if (j <= jmax) {
                    float s = 0.f;
                    #pragma unroll
                    for (int d = 0; d < 32; d++) s += q[d] * Ks[j][d];
                    sarr[j] = s;
                    tmax = fmaxf(tmax, s);
                }
            }
            float newm = fmaxf(mrun, tmax);
            float alpha = __expf(mrun - newm);
            l *= alpha;
            #pragma unroll
            for (int d = 0; d < 16; d++) acc[d] *= alpha;
            #pragma unroll
            for (int j = 0; j < 32; j++) {
                if (j <= jmax) {
                    float p = __expf(sarr[j] - newm);
                    l += p;
                    #pragma unroll
                    for (int d = 0; d < 16; d++) acc[d] += p * Vs[j][dhalf * 16 + d];
                }
            }
            mrun = newm;
        }
        __syncthreads();
    }
    float inv = 1.f / l;
    float* xr = x + (b * 512 + qi) * 256 + h * 32 + dhalf * 16;
    #pragma unroll
    for (int d = 0; d < 16; d++) xr[d] += acc[d] * inv;
}

// ---------------- deterministic global mean/std (ddof=1) + normalize ------------
__global__ void reduce_k(const float* __restrict__ e) {
    __shared__ double s1[256], s2[256];
    const int t = threadIdx.x;
    double s = 0.0, ss = 0.0;
    for (int i = blockIdx.x * 256 + t; i < 262144; i += 256 * 256) {
        double v = (double)e[i];
        s += v;
        ss += v * v;
    }
    s1[t] = s;
    s2[t] = ss;
    __syncthreads();
    for (int k = 128; k > 0; k >>= 1) {
        if (t < k) { s1[t] += s1[t + k]; s2[t] += s2[t + k]; }
        __syncthreads();
    }
    if (t == 0) { g_part[blockIdx.x] = s1[0]; g_part[256 + blockIdx.x] = s2[0]; }
}

__global__ void norm_k(float* e) {
    __shared__ double s1[256], s2[256];
    const int t = threadIdx.x;
    s1[t] = g_part[t];
    s2[t] = g_part[256 + t];
    __syncthreads();
    for (int k = 128; k > 0; k >>= 1) {
        if (t < k) { s1[t] += s1[t + k]; s2[t] += s2[t + k]; }
        __syncthreads();
    }
    const double n = 262144.0;
    double mu = s1[0] / n;
    double var = (s2[0] - n * mu * mu) / (n - 1.0);
    float inv = (float)(1.0 / sqrt(var));
    float fmu = (float)mu;
    int i = (blockIdx.x * 256 + t) * 4;
    float4 v = *(float4*)&e[i];
    v.x = (v.x - fmu) * inv + 1e-10f;
    v.y = (v.y - fmu) * inv + 1e-10f;
    v.z = (v.z - fmu) * inv + 1e-10f;
    v.w = (v.w - fmu) * inv + 1e-10f;
    *(float4*)&e[i] = v;
}

// ---------------- launch ----------------
extern "C" void kernel_launch(void* const* d_in, const int* in_sizes, int n_in,
                              void* d_out, int out_size) {
    const float* state   = (const float*)d_in[0];
    const float* conv_w1 = (const float*)d_in[1];
    const float* conv_b1 = (const float*)d_in[2];
    const float* conv_w2 = (const float*)d_in[3];
    const float* conv_b2 = (const float*)d_in[4];
    const float* conv_w3 = (const float*)d_in[5];
    const float* conv_b3 = (const float*)d_in[6];
    const float* pre_w   = (const float*)d_in[7];
    const float* pre_b   = (const float*)d_in[8];
    const float* pos_w   = (const float*)d_in[9];
    const float* ln1_g   = (const float*)d_in[10];
    const float* ln1_b   = (const float*)d_in[11];
    const float* enc_w   = (const float*)d_in[12];
    const float* enc_b   = (const float*)d_in[13];
    const float* ln2_g   = (const float*)d_in[14];
    const float* ln2_b   = (const float*)d_in[15];
    const float* ffn_w1  = (const float*)d_in[16];
    const float* ffn_b1  = (const float*)d_in[17];
    const float* ffn_w2  = (const float*)d_in[18];
    const float* ffn_b2  = (const float*)d_in[19];
    const float* emb_w   = (const float*)d_in[20];
    const float* emb_b   = (const float*)d_in[21];
    float* out = (float*)d_out;

    float *x1, *x2, *x3, *x, *xn, *cb, *hb;
    cudaGetSymbolAddress((void**)&x1, g_x1);
    cudaGetSymbolAddress((void**)&x2, g_x2);
    cudaGetSymbolAddress((void**)&x3, g_x3);
    cudaGetSymbolAddress((void**)&x,  g_x);
    cudaGetSymbolAddress((void**)&xn, g_xn);
    cudaGetSymbolAddress((void**)&cb, g_c);
    cudaGetSymbolAddress((void**)&hb, g_h);

    // conv stem: all three tensorized implicit GEMM
    conv1t_k<<<dim3(12, 1024), 256>>>(state, conv_w1, conv_b1, x1);
    convt_k<48, 60, 24, 30, 8><<<1024, 256>>>(x1, conv_w2, conv_b2, x2);
    convt_k<24, 30, 12, 15, 4><<<1024, 128>>>(x2, conv_w3, conv_b3, x3);

    // pre-projection + positional  (64x64 tiles, S=9, cp.async)
    gemm64_k<1><<<dim3(4, 16, 9), 256>>>(x3, pre_w, pre_b, pos_w, x,
                                         1024, 256, 2880, 9, 320);

    for (int k = 0; k < 4; k++) {
        ln_k<<<128, 256>>>(x, ln1_g + k * 256, ln1_b + k * 256, xn);
        gemm32_k<0><<<dim3(12, 32, 2), 256>>>(xn, enc_w + k * 256 * 768, enc_b + k * 768,
                                              nullptr, cb, 1024, 768, 256, 2, 128);
        attn_k<<<dim3(8, 16), 128>>>(cb, x);
        ln_k<<<128, 256>>>(x, ln2_g + k * 256, ln2_b + k * 256, x);
        gemm32_k<2><<<dim3(16, 32, 2), 256>>>(x, ffn_w1 + k * 256 * 1024, ffn_b1 + k * 1024,
                                              nullptr, hb, 1024, 1024, 256, 2, 128);
        gemm32_k<3><<<dim3(4, 32, 4), 256>>>(hb, ffn_w2 + k * 1024 * 256, ffn_b2 + k * 256,
                                             x, x, 1024, 256, 1024, 4, 256);
    }

    gemm32_k<0><<<dim3(4, 32, 4), 256>>>(x, emb_w, emb_b, nullptr, out,
                                         1024, 256, 256, 4, 64);

    reduce_k<<<256, 256>>>(out);
    norm_k<<<256, 256>>>(out);
}

// round 15
// speedup vs baseline: 1.1601x; 1.1465x over previous
#include <cuda_runtime.h>
#include <math.h>

// ---------------- scratch (device globals; no allocation allowed) ----------------
__device__ float g_x1[1024 * 16 * 48 * 60];   // conv1 out
__device__ float g_x2[1024 * 16 * 24 * 30];   // conv2 out
__device__ float g_x3[1024 * 16 * 12 * 15];   // conv3 out (= tokens x 2880)
__device__ float g_x [1024 * 256];            // residual stream
__device__ float g_xn[1024 * 256];            // ln1 output
__device__ float g_c [1024 * 768];            // qkv
__device__ float g_h [1024 * 1024];           // ffn hidden
__device__ float g_sp[4 * 1024 * 1024];       // split-K partials
__device__ unsigned g_cnt[512];               // per-tile arrival counters
__device__ double g_part[512];                // partial sums / sumsq

// ---------------- helpers ----------------
__device__ __forceinline__ unsigned f2tf(float f) {
    unsigned u;
    asm("cvt.rna.tf32.f32 %0, %1;" : "=r"(u) : "f"(f));
    return u;
}
__device__ __forceinline__ void mma_tf32(float c[4], unsigned a0, unsigned a1,
                                         unsigned a2, unsigned a3,
                                         unsigned b0, unsigned b1) {
    asm volatile(
        "mma.sync.aligned.m16n8k8.row.col.f32.tf32.tf32.f32 "
        "{%0,%1,%2,%3}, {%4,%5,%6,%7}, {%8,%9}, {%0,%1,%2,%3};\n"
        : "+f"(c[0]), "+f"(c[1]), "+f"(c[2]), "+f"(c[3])
        : "r"(a0), "r"(a1), "r"(a2), "r"(a3), "r"(b0), "r"(b1));
}
__device__ __forceinline__ void cpasync16(const void* smem_dst, const void* gsrc) {
    unsigned s = (unsigned)__cvta_generic_to_shared(smem_dst);
    asm volatile("cp.async.cg.shared.global [%0], [%1], 16;" :: "r"(s), "l"(gsrc));
}
__device__ __forceinline__ void cp_commit() {
    asm volatile("cp.async.commit_group;");
}
template <int N>
__device__ __forceinline__ void cp_wait() {
    asm volatile("cp.async.wait_group %0;" :: "n"(N));
}

// ---------------- conv1 tensorized: CIN=3, 96x120 -> 48x60, strip of 4 out rows --
// Halo plane WS=128 with interior at column 4 (16B aligned): interior rows staged
// via cp.async (raw fp32 bits -> tf32 truncation in MMA); borders zero-filled.
__global__ void __launch_bounds__(256) conv1t_k(
    const float* __restrict__ in, const float* __restrict__ w,
    const float* __restrict__ bias, float* __restrict__ out) {
    constexpr int WS = 128, RS = 10, PLANE = RS * WS;
    constexpr int M = 240;                              // 4 out rows x 60
    __shared__ unsigned sIn[3 * PLANE];                 // 3 ci planes
    __shared__ unsigned Bw[48 * 17];                    // weights [k][co]

    const int strip = blockIdx.x;        // 0..11
    const int n = blockIdx.y;            // image
    const int t = threadIdx.x;
    const int warp = t >> 5, lane = t & 31;
    const int g = lane >> 2, tig = lane & 3;

    // interior staging: 3 ci x 10 rows x 30 chunks of 16B
    const float* inp = in + (size_t)n * 3 * 96 * 120;
    for (int j = t; j < 900; j += 256) {
        int ci = j / 300, rem = j % 300;
        int r = rem / 30, chunk = rem % 30;
        int gih = strip * 8 + r - 1;
        if (gih >= 0 && gih < 96)
            cpasync16(&sIn[ci * PLANE + r * WS + 4 + chunk * 4],
                      inp + (ci * 96 + gih) * 120 + chunk * 4);
    }
    cp_commit();

    // stage weights: w layout [co][ci][kh][kw] = co*48 + k
    for (int i = t; i < 48 * 16; i += 256) {
        int co = i / 48, k = i % 48;
        Bw[k * 17 + co] = f2tf(w[i]);
    }
    // zero halo columns (c=3 left, c=124 right) for all rows
    for (int j = t; j < 60; j += 256) {
        int ci = j / 20, rem = j % 20;
        int r = rem >> 1, side = rem & 1;
        sIn[ci * PLANE + r * WS + (side ? 124 : 3)] = 0u;
    }
    // zero invalid rows (top halo of strip 0, bottom halo of strip 11), c in [3,125)
    if (strip == 0 || strip == 11) {
        int r = (strip == 0) ? 0 : 9;
        for (int j = t; j < 3 * 122; j += 256) {
            int ci = j / 122, cc = j % 122;
            sIn[ci * PLANE + r * WS + 3 + cc] = 0u;
        }
    }
    cp_wait<0>();
    __syncthreads();

    // B fragments (register-cached): 6 k-steps of 8
    unsigned bf[6][2][2];
    #pragma unroll
    for (int kf = 0; kf < 6; kf++)
        #pragma unroll
        for (int nf = 0; nf < 2; nf++) {
            int kb = kf * 8 + tig;
            bf[kf][nf][0] = Bw[kb * 17 + nf * 8 + g];
            bf[kf][nf][1] = Bw[(kb + 4) * 17 + nf * 8 + g];
        }

    float acc[2][2][4];
    #pragma unroll
    for (int mt = 0; mt < 2; mt++)
        #pragma unroll
        for (int nf = 0; nf < 2; nf++)
            #pragma unroll
            for (int r = 0; r < 4; r++) acc[mt][nf][r] = 0.f;

    // rowoff: window col base c = ow*2 + 3 (+ tap&3), row = ohl*2 (+ tap>>2)
    int rowoff[2][2];
    #pragma unroll
    for (int mt = 0; mt < 2; mt++)
        #pragma unroll
        for (int r = 0; r < 2; r++) {
            int m = (warp * 2 + mt) * 16 + g + r * 8;
            if (m >= M) m = M - 1;
            int ohl = m / 60, ow = m % 60;
            rowoff[mt][r] = (ohl * 2) * WS + ow * 2 + 3;
        }

    #pragma unroll
    for (int mt = 0; mt < 2; mt++) {
        #pragma unroll
        for (int kf = 0; kf < 6; kf++) {
            unsigned a[4];
            #pragma unroll
            for (int half = 0; half < 2; half++) {
                int k5 = kf * 8 + tig + half * 4;
                int ci = k5 >> 4, tap = k5 & 15;
                int off = ci * PLANE + (tap >> 2) * WS + (tap & 3);
                a[half * 2 + 0] = sIn[rowoff[mt][0] + off];
                a[half * 2 + 1] = sIn[rowoff[mt][1] + off];
            }
            #pragma unroll
            for (int nf = 0; nf < 2; nf++)
                mma_tf32(acc[mt][nf], a[0], a[1], a[2], a[3],
                         bf[kf][nf][0], bf[kf][nf][1]);
        }
    }

    #pragma unroll
    for (int mt = 0; mt < 2; mt++)
        #pragma unroll
        for (int r = 0; r < 2; r++) {
            int m = (warp * 2 + mt) * 16 + g + r * 8;
            if (m < M) {
                int oh = strip * 4 + m / 60, ow = m % 60;
                #pragma unroll
                for (int nf = 0; nf < 2; nf++) {
                    int co = nf * 8 + 2 * tig;
                    float v0 = acc[mt][nf][2 * r + 0] + __ldg(&bias[co]);
                    float v1 = acc[mt][nf][2 * r + 1] + __ldg(&bias[co + 1]);
                    out[((n * 16 + co) * 48 + oh) * 60 + ow] = fmaxf(v0, 0.f);
                    out[((n * 16 + co + 1) * 48 + oh) * 60 + ow] = fmaxf(v1, 0.f);
                }
            }
        }
}

// ---------------- tensorized conv (CIN=16, COUT=16, 4x4, stride2, pad1) --------
template <int Hin, int Win, int Hout, int Wout, int NW>
__global__ void __launch_bounds__(NW * 32) convt_k(
    const float* __restrict__ in, const float* __restrict__ w,
    const float* __restrict__ bias, float* __restrict__ out) {
    constexpr int HS = Hin + 2, WS = Win + 2;
    constexpr int PLANE = HS * WS;
    constexpr int M = Hout * Wout;
    constexpr int MT_TOT = (M + 15) / 16;
    constexpr int MT_PW = (MT_TOT + NW - 1) / NW;

    __shared__ unsigned sIn[2 * PLANE];
    __shared__ unsigned Bw[256 * 17];

    const int n = blockIdx.x;
    const int t = threadIdx.x;
    const int warp = t >> 5, lane = t & 31;
    const int g = lane >> 2, tig = lane & 3;

    for (int i = t; i < 256 * 16; i += NW * 32) {
        int co = i >> 8, k = i & 255;
        Bw[k * 17 + co] = f2tf(w[i]);
    }

    int rowoff[MT_PW][2];
    #pragma unroll
    for (int mt = 0; mt < MT_PW; mt++) {
        #pragma unroll
        for (int r = 0; r < 2; r++) {
            int m = (warp * MT_PW + mt) * 16 + g + r * 8;
            if (m >= M) m = M - 1;
            int oh = m / Wout, ow = m % Wout;
            rowoff[mt][r] = (oh * 2) * WS + ow * 2;
        }
    }

    float acc[MT_PW][2][4];
    #pragma unroll
    for (int mt = 0; mt < MT_PW; mt++)
        #pragma unroll
        for (int nf = 0; nf < 2; nf++)
            #pragma unroll
            for (int r = 0; r < 4; r++) acc[mt][nf][r] = 0.f;

    const float* inp = in + (size_t)n * 16 * Hin * Win;

    #pragma unroll 1
    for (int cg = 0; cg < 8; cg++) {
        __syncthreads();
        for (int j = t; j < 2 * PLANE; j += NW * 32) {
            int ci_l = j / PLANE, rr = j % PLANE;
            int r = rr / WS, c = rr % WS;
            int gih = r - 1, giw = c - 1;
            float v = 0.f;
            if (gih >= 0 && gih < Hin && giw >= 0 && giw < Win)
                v = inp[((cg * 2 + ci_l) * Hin + gih) * Win + giw];
            sIn[j] = f2tf(v);
        }
        __syncthreads();

        unsigned bf[4][2][2];
        #pragma unroll
        for (int kf = 0; kf < 4; kf++)
            #pragma unroll
            for (int nf = 0; nf < 2; nf++) {
                int kb = cg * 32 + kf * 8 + tig;
                bf[kf][nf][0] = Bw[kb * 17 + nf * 8 + g];
                bf[kf][nf][1] = Bw[(kb + 4) * 17 + nf * 8 + g];
            }

        #pragma unroll
        for (int mt = 0; mt < MT_PW; mt++) {
            #pragma unroll
            for (int kf = 0; kf < 4; kf++) {
                unsigned a[4];
                #pragma unroll
                for (int half = 0; half < 2; half++) {
                    int k5 = kf * 8 + tig + half * 4;
                    int ci_l = k5 >> 4, tap = k5 & 15;
                    int off = ci_l * PLANE + (tap >> 2) * WS + (tap & 3);
                    a[half * 2 + 0] = sIn[rowoff[mt][0] + off];
                    a[half * 2 + 1] = sIn[rowoff[mt][1] + off];
                }
                #pragma unroll
                for (int nf = 0; nf < 2; nf++)
                    mma_tf32(acc[mt][nf], a[0], a[1], a[2], a[3],
                             bf[kf][nf][0], bf[kf][nf][1]);
            }
        }
    }

    #pragma unroll
    for (int mt = 0; mt < MT_PW; mt++) {
        #pragma unroll
        for (int r = 0; r < 2; r++) {
            int m = (warp * MT_PW + mt) * 16 + g + r * 8;
            if (m < M) {
                int oh = m / Wout, ow = m % Wout;
                #pragma unroll
                for (int nf = 0; nf < 2; nf++) {
                    int co = nf * 8 + 2 * tig;
                    float v0 = acc[mt][nf][2 * r + 0] + __ldg(&bias[co]);
                    float v1 = acc[mt][nf][2 * r + 1] + __ldg(&bias[co + 1]);
                    out[((n * 16 + co) * Hout + oh) * Wout + ow] = fmaxf(v0, 0.f);
                    out[((n * 16 + co + 1) * Hout + oh) * Wout + ow] = fmaxf(v1, 0.f);
                }
            }
        }
    }
}

template <int EPI>
__device__ __forceinline__ float epi_apply(float v, int m, int n, int N,
                                           const float* __restrict__ extra) {
    if (EPI == 1) v += extra[(m & 511) * N + n];
    if (EPI == 2) v = v * normcdff(v);
    if (EPI == 3) v += extra[m * N + n];
    return v;
}

// ---------------- GEMM A: 32x64 tile, 256 threads, warp tile 16x16, cp.async ---
template <int EPI>
__global__ void __launch_bounds__(256) gemm32_k(
    const float* __restrict__ A, const float* __restrict__ B,
    const float* __restrict__ bias, const float* __restrict__ extra,
    float* __restrict__ C, int M, int N, int K, int S, int Kc) {
    __shared__ unsigned As[2][32][36];
    __shared__ unsigned Bs[2][32][68];

    const int t = threadIdx.x;
    const int m0 = blockIdx.y * 32, n0 = blockIdx.x * 64;
    const int z = blockIdx.z;
    const int kb0 = z * Kc;
    const int warp = t >> 5, lane = t & 31;
    const int g = lane >> 2, tig = lane & 3;
    const int wm = (warp >> 2) * 16;
    const int wn = (warp & 3) * 16;

    float acc[2][4];
    #pragma unroll
    for (int nf = 0; nf < 2; nf++)
        #pragma unroll
        for (int r = 0; r < 4; r++) acc[nf][r] = 0.f;

    const int a_row = t >> 3, a_col = (t & 7) * 4;
    const int b_row = t >> 4, b_col = (t & 15) * 4;
    const int NC = Kc >> 5;
    const float* Ab = A + kb0 + (size_t)(m0 + a_row) * K + a_col;
    const float* Bb0 = B + (size_t)(kb0 + b_row) * N + n0 + b_col;
    const float* Bb1 = B + (size_t)(kb0 + b_row + 16) * N + n0 + b_col;

    cpasync16(&As[0][a_row][a_col], Ab);
    cpasync16(&Bs[0][b_row][b_col], Bb0);
    cpasync16(&Bs[0][b_row + 16][b_col], Bb1);
    cp_commit();

    for (int c = 0; c < NC; c++) {
        const int s = c & 1;
        if (c + 1 < NC) {
            int k0 = (c + 1) * 32;
            cpasync16(&As[s ^ 1][a_row][a_col], Ab + k0);
            cpasync16(&Bs[s ^ 1][b_row][b_col], Bb0 + (size_t)k0 * N);
            cpasync16(&Bs[s ^ 1][b_row + 16][b_col], Bb1 + (size_t)k0 * N);
        }
        cp_commit();
        cp_wait<1>();
        __syncthreads();

        #pragma unroll
        for (int ks = 0; ks < 4; ks++) {
            int k8 = ks * 8;
            unsigned a0 = As[s][wm + g][k8 + tig];
            unsigned a1 = As[s][wm + g + 8][k8 + tig];
            unsigned a2 = As[s][wm + g][k8 + tig + 4];
            unsigned a3 = As[s][wm + g + 8][k8 + tig + 4];
            #pragma unroll
            for (int nf = 0; nf < 2; nf++) {
                int nc = wn + nf * 8 + g;
                unsigned b0 = Bs[s][k8 + tig][nc];
                unsigned b1 = Bs[s][k8 + tig + 4][nc];
                mma_tf32(acc[nf], a0, a1, a2, a3, b0, b1);
            }
        }
        __syncthreads();
    }

    if (S == 1) {
        #pragma unroll
        for (int half = 0; half < 2; half++) {
            int m = m0 + wm + g + half * 8;
            #pragma unroll
            for (int nf = 0; nf < 2; nf++) {
                int n = n0 + wn + nf * 8 + 2 * tig;
                float v0 = epi_apply<EPI>(acc[nf][2 * half] + bias[n], m, n, N, extra);
                float v1 = epi_apply<EPI>(acc[nf][2 * half + 1] + bias[n + 1], m, n + 1, N, extra);
                *(float2*)&C[m * N + n] = make_float2(v0, v1);
            }
        }
        return;
    }

    float* pz = g_sp + (size_t)z * M * N;
    #pragma unroll
    for (int half = 0; half < 2; half++) {
        int m = m0 + wm + g + half * 8;
        #pragma unroll
        for (int nf = 0; nf < 2; nf++) {
            int n = n0 + wn + nf * 8 + 2 * tig;
            *(float2*)&pz[m * N + n] = make_float2(acc[nf][2 * half], acc[nf][2 * half + 1]);
        }
    }
    __threadfence();
    __syncthreads();
    __shared__ unsigned s_old;
    const int tile = blockIdx.y * gridDim.x + blockIdx.x;
    if (t == 0) s_old = atomicAdd(&g_cnt[tile], 1);
    __syncthreads();
    if (s_old != (unsigned)(S - 1)) return;
    __threadfence();

    #pragma unroll
    for (int half = 0; half < 2; half++) {
        int m = m0 + wm + g + half * 8;
        #pragma unroll
        for (int nf = 0; nf < 2; nf++) {
            int n = n0 + wn + nf * 8 + 2 * tig;
            float v0 = bias[n], v1 = bias[n + 1];
            for (int s2 = 0; s2 < S; s2++) {
                float2 pv = *(const float2*)&g_sp[(size_t)s2 * M * N + m * N + n];
                v0 += pv.x; v1 += pv.y;
            }
            v0 = epi_apply<EPI>(v0, m, n, N, extra);
            v1 = epi_apply<EPI>(v1, m, n + 1, N, extra);
            *(float2*)&C[m * N + n] = make_float2(v0, v1);
        }
    }
    if (t == 0) g_cnt[tile] = 0;
}

// ---------------- GEMM B: 64x64 tile, 256 threads, warp tile 32x16, cp.async ---
template <int EPI>
__global__ void __launch_bounds__(256) gemm64_k(
    const float* __restrict__ A, const float* __restrict__ B,
    const float* __restrict__ bias, const float* __restrict__ extra,
    float* __restrict__ C, int M, int N, int K, int S, int Kc) {
    __shared__ unsigned As[2][64][36];
    __shared__ unsigned Bs[2][32][68];

    const int t = threadIdx.x;
    const int m0 = blockIdx.y * 64, n0 = blockIdx.x * 64;
    const int z = blockIdx.z;
    const int kb0 = z * Kc;
    const int warp = t >> 5, lane = t & 31;
    const int g = lane >> 2, tig = lane & 3;
    const int wm = (warp >> 2) * 32;
    const int wn = (warp & 3) * 16;

    float acc[2][2][4];
    #pragma unroll
    for (int mt = 0; mt < 2; mt++)
        #pragma unroll
        for (int nf = 0; nf < 2; nf++)
            #pragma unroll
            for (int r = 0; r < 4; r++) acc[mt][nf][r] = 0.f;

    const int a_row = t >> 2, a_colb = (t & 3) * 8;
    const int b_row = t >> 3, b_colb = (t & 7) * 8;
    const int NC = Kc >> 5;
    const float* Ab = A + kb0 + (size_t)(m0 + a_row) * K + a_colb;
    const float* Bb = B + (size_t)(kb0 + b_row) * N + n0 + b_colb;

    cpasync16(&As[0][a_row][a_colb], Ab);
    cpasync16(&As[0][a_row][a_colb + 4], Ab + 4);
    cpasync16(&Bs[0][b_row][b_colb], Bb);
    cpasync16(&Bs[0][b_row][b_colb + 4], Bb + 4);
    cp_commit();

    for (int c = 0; c < NC; c++) {
        const int s = c & 1;
        if (c + 1 < NC) {
            int k0 = (c + 1) * 32;
            cpasync16(&As[s ^ 1][a_row][a_colb], Ab + k0);
            cpasync16(&As[s ^ 1][a_row][a_colb + 4], Ab + k0 + 4);
            cpasync16(&Bs[s ^ 1][b_row][b_colb], Bb + (size_t)k0 * N);
            cpasync16(&Bs[s ^ 1][b_row][b_colb + 4], Bb + (size_t)k0 * N + 4);
        }
        cp_commit();
        cp_wait<1>();
        __syncthreads();

        #pragma unroll
        for (int ks = 0; ks < 4; ks++) {
            const int k8 = ks * 8;
            unsigned a[2][4], bf[2][2];
            #pragma unroll
            for (int mt = 0; mt < 2; mt++) {
                int mr = wm + mt * 16 + g;
                a[mt][0] = As[s][mr][k8 + tig];
                a[mt][1] = As[s][mr + 8][k8 + tig];
                a[mt][2] = As[s][mr][k8 + tig + 4];
                a[mt][3] = As[s][mr + 8][k8 + tig + 4];
            }
            #pragma unroll
            for (int nf = 0; nf < 2; nf++) {
                int nc = wn + nf * 8 + g;
                bf[nf][0] = Bs[s][k8 + tig][nc];
                bf[nf][1] = Bs[s][k8 + tig + 4][nc];
            }
            #pragma unroll
            for (int mt = 0; mt < 2; mt++)
                #pragma unroll
                for (int nf = 0; nf < 2; nf++)
                    mma_tf32(acc[mt][nf], a[mt][0], a[mt][1], a[mt][2], a[mt][3],
                             bf[nf][0], bf[nf][1]);
        }
        __syncthreads();
    }

    if (S == 1) {
        #pragma unroll
        for (int mt = 0; mt < 2; mt++)
            #pragma unroll
            for (int half = 0; half < 2; half++) {
                int m = m0 + wm + mt * 16 + g + half * 8;
                #pragma unroll
                for (int nf = 0; nf < 2; nf++) {
                    int n = n0 + wn + nf * 8 + 2 * tig;
                    float v0 = epi_apply<EPI>(acc[mt][nf][2 * half] + bias[n], m, n, N, extra);
                    float v1 = epi_apply<EPI>(acc[mt][nf][2 * half + 1] + bias[n + 1], m, n + 1, N, extra);
                    *(float2*)&C[m * N + n] = make_float2(v0, v1);
                }
            }
        return;
    }

    float* pz = g_sp + (size_t)z * M * N;
    #pragma unroll
    for (int mt = 0; mt < 2; mt++)
        #pragma unroll
        for (int half = 0; half < 2; half++) {
            int m = m0 + wm + mt * 16 + g + half * 8;
            #pragma unroll
            for (int nf = 0; nf < 2; nf++) {
                int n = n0 + wn + nf * 8 + 2 * tig;
                *(float2*)&pz[m * N + n] =
                    make_float2(acc[mt][nf][2 * half], acc[mt][nf][2 * half + 1]);
            }
        }
    __threadfence();
    __syncthreads();
    __shared__ unsigned s_old;
    const int tile = blockIdx.y * gridDim.x + blockIdx.x;
    if (t == 0) s_old = atomicAdd(&g_cnt[tile], 1);
    __syncthreads();
    if (s_old != (unsigned)(S - 1)) return;
    __threadfence();

    #pragma unroll
    for (int mt = 0; mt < 2; mt++)
        #pragma unroll
        for (int half = 0; half < 2; half++) {
            int m = m0 + wm + mt * 16 + g + half * 8;
            #pragma unroll
            for (int nf = 0; nf < 2; nf++) {
                int n = n0 + wn + nf * 8 + 2 * tig;
                float v0 = bias[n], v1 = bias[n + 1];
                for (int s2 = 0; s2 < S; s2++) {
                    float2 pv = *(const float2*)&g_sp[(size_t)s2 * M * N + m * N + n];
                    v0 += pv.x; v1 += pv.y;
                }
                v0 = epi_apply<EPI>(v0, m, n, N, extra);
                v1 = epi_apply<EPI>(v1, m, n + 1, N, extra);
                *(float2*)&C[m * N + n] = make_float2(v0, v1);
            }
        }
    if (t == 0) g_cnt[tile] = 0;
}

// ---------------- layernorm: one warp per row, shuffle reductions ----------------
__global__ void __launch_bounds__(256) ln_k(
    const float* __restrict__ in, const float* __restrict__ gw,
    const float* __restrict__ bw, float* __restrict__ out) {
    const int t = threadIdx.x, warp = t >> 5, lane = t & 31;
    const int row = blockIdx.x * 8 + warp;
    const float4* r = (const float4*)(in + row * 256);
    float4 v0 = r[lane], v1 = r[lane + 32];
    float s = v0.x + v0.y + v0.z + v0.w + v1.x + v1.y + v1.z + v1.w;
    #pragma unroll
    for (int o = 16; o > 0; o >>= 1) s += __shfl_xor_sync(0xffffffffu, s, o);
    float mu = s * (1.f / 256.f);
    float d0x = v0.x - mu, d0y = v0.y - mu, d0z = v0.z - mu, d0w = v0.w - mu;
    float d1x = v1.x - mu, d1y = v1.y - mu, d1z = v1.z - mu, d1w = v1.w - mu;
    float ss = d0x * d0x + d0y * d0y + d0z * d0z + d0w * d0w
             + d1x * d1x + d1y * d1y + d1z * d1z + d1w * d1w;
    #pragma unroll
    for (int o = 16; o > 0; o >>= 1) ss += __shfl_xor_sync(0xffffffffu, ss, o);
    float inv = rsqrtf(ss * (1.f / 256.f) + 1e-5f);
    const float4* g4 = (const float4*)gw;
    const float4* b4 = (const float4*)bw;
    float4 ga = g4[lane], gb = g4[lane + 32];
    float4 ba = b4[lane], bb = b4[lane + 32];
    float4* o4 = (float4*)(out + row * 256);
    o4[lane] = make_float4(d0x * inv * ga.x + ba.x, d0y * inv * ga.y + ba.y,
                           d0z * inv * ga.z + ba.z, d0w * inv * ga.w + ba.w);
    o4[lane + 32] = make_float4(d1x * inv * gb.x + bb.x, d1y * inv * gb.y + bb.y,
                                d1z * inv * gb.z + bb.z, d1w * inv * gb.w + bb.w);
}

// ---------------- causal attention: 2 threads/query, cp.async double-buffer -----
__global__ void __launch_bounds__(128) attn_k(const float* __restrict__ c,
                                              float* __restrict__ x) {
    __shared__ float Ks[2][32][32];
    __shared__ float Vs[2][32][32];
    const int t = threadIdx.x;            // 128 threads
    const int qt = blockIdx.x;            // 8 query tiles of 64
    const int bh = blockIdx.y;            // 16 (b,h)
    const int b = bh >> 3, h = bh & 7;
    const int qi = qt * 64 + (t & 63);
    const int dhalf = t >> 6;             // 0 or 1: V dims [dhalf*16, +16)
    const float* crow = c + (b * 512 + qi) * 768 + h * 32;

    const float SC = 0.17677669529663687f;  // 1/sqrt(32)
    float q[32];
    #pragma unroll
    for (int d4 = 0; d4 < 8; d4++) {
        float4 qv = *(const float4*)(crow + d4 * 4);
        q[4 * d4 + 0] = qv.x * SC;
        q[4 * d4 + 1] = qv.y * SC;
        q[4 * d4 + 2] = qv.z * SC;
        q[4 * d4 + 3] = qv.w * SC;
    }
    float acc[16];
    #pragma unroll
    for (int d = 0; d < 16; d++) acc[d] = 0.f;
    float mrun = -1e30f, l = 0.f;

    const int ntiles = qt * 2 + 2;        // covers kb = 0..qt*64+32
    const int jj = t >> 2, q8 = (t & 3) * 8;
    const float* kvbase = c + ((size_t)b * 512 + jj) * 768 + 256 + h * 32 + q8;

    // prologue: tile 0
    cpasync16(&Ks[0][jj][q8], kvbase);
    cpasync16(&Ks[0][jj][q8 + 4], kvbase + 4);
    cpasync16(&Vs[0][jj][q8], kvbase + 256);
    cpasync16(&Vs[0][jj][q8 + 4], kvbase + 260);
    cp_commit();

    for (int ti = 0; ti < ntiles; ti++) {
        const int s = ti & 1;
        if (ti + 1 < ntiles) {
            const float* kr = kvbase + (size_t)(ti + 1) * 32 * 768;
            cpasync16(&Ks[s ^ 1][jj][q8], kr);
            cpasync16(&Ks[s ^ 1][jj][q8 + 4], kr + 4);
            cpasync16(&Vs[s ^ 1][jj][q8], kr + 256);
            cpasync16(&Vs[s ^ 1][jj][q8 + 4], kr + 260);
        }
        cp_commit();
        cp_wait<1>();
        __syncthreads();

        const int kb = ti * 32;
        if (kb <= qi) {
            int jmax = qi - kb;
            if (jmax > 31) jmax = 31;
            float sarr[32];
            float tmax = -1e30f;
            #pragma unroll
            for (int j = 0; j < 32; j++) {
                if (j <= jmax) {
                    float sc = 0.f;
                    #pragma unroll
                    for (int d = 0; d < 32; d++) sc += q[d] * Ks[s][j][d];
                    sarr[j] = sc;
                    tmax = fmaxf(tmax, sc);
                }
            }
            float newm = fmaxf(mrun, tmax);
            float alpha = __expf(mrun - newm);
            l *= alpha;
            #pragma unroll
            for (int d = 0; d < 16; d++) acc[d] *= alpha;
            #pragma unroll
            for (int j = 0; j < 32; j++) {
                if (j <= jmax) {
                    float p = __expf(sarr[j] - newm);
                    l += p;
                    #pragma unroll
                    for (int d = 0; d < 16; d++) acc[d] += p * Vs[s][j][dhalf * 16 + d];
                }
            }
            mrun = newm;
        }
        __syncthreads();
    }
    float inv = 1.f / l;
    float* xr = x + (b * 512 + qi) * 256 + h * 32 + dhalf * 16;
    #pragma unroll
    for (int d = 0; d < 16; d++) xr[d] += acc[d] * inv;
}

// ---------------- deterministic global mean/std (ddof=1) + normalize ------------
__global__ void reduce_k(const float* __restrict__ e) {
    __shared__ double s1[256], s2[256];
    const int t = threadIdx.x;
    double s = 0.0, ss = 0.0;
    for (int i = blockIdx.x * 256 + t; i < 262144; i += 256 * 256) {
        double v = (double)e[i];
        s += v;
        ss += v * v;
    }
    s1[t] = s;
    s2[t] = ss;
    __syncthreads();
    for (int k = 128; k > 0; k >>= 1) {
        if (t < k) { s1[t] += s1[t + k]; s2[t] += s2[t + k]; }
        __syncthreads();
    }
    if (t == 0) { g_part[blockIdx.x] = s1[0]; g_part[256 + blockIdx.x] = s2[0]; }
}

__global__ void norm_k(float* e) {
    __shared__ double s1[256], s2[256];
    const int t = threadIdx.x;
    s1[t] = g_part[t];
    s2[t] = g_part[256 + t];
    __syncthreads();
    for (int k = 128; k > 0; k >>= 1) {
        if (t < k) { s1[t] += s1[t + k]; s2[t] += s2[t + k]; }
        __syncthreads();
    }
    const double n = 262144.0;
    double mu = s1[0] / n;
    double var = (s2[0] - n * mu * mu) / (n - 1.0);
    float inv = (float)(1.0 / sqrt(var));
    float fmu = (float)mu;
    int i = (blockIdx.x * 256 + t) * 4;
    float4 v = *(float4*)&e[i];
    v.x = (v.x - fmu) * inv + 1e-10f;
    v.y = (v.y - fmu) * inv + 1e-10f;
    v.z = (v.z - fmu) * inv + 1e-10f;
    v.w = (v.w - fmu) * inv + 1e-10f;
    *(float4*)&e[i] = v;
}

// ---------------- launch ----------------
extern "C" void kernel_launch(void* const* d_in, const int* in_sizes, int n_in,
                              void* d_out, int out_size) {
    const float* state   = (const float*)d_in[0];
    const float* conv_w1 = (const float*)d_in[1];
    const float* conv_b1 = (const float*)d_in[2];
    const float* conv_w2 = (const float*)d_in[3];
    const float* conv_b2 = (const float*)d_in[4];
    const float* conv_w3 = (const float*)d_in[5];
    const float* conv_b3 = (const float*)d_in[6];
    const float* pre_w   = (const float*)d_in[7];
    const float* pre_b   = (const float*)d_in[8];
    const float* pos_w   = (const float*)d_in[9];
    const float* ln1_g   = (const float*)d_in[10];
    const float* ln1_b   = (const float*)d_in[11];
    const float* enc_w   = (const float*)d_in[12];
    const float* enc_b   = (const float*)d_in[13];
    const float* ln2_g   = (const float*)d_in[14];
    const float* ln2_b   = (const float*)d_in[15];
    const float* ffn_w1  = (const float*)d_in[16];
    const float* ffn_b1  = (const float*)d_in[17];
    const float* ffn_w2  = (const float*)d_in[18];
    const float* ffn_b2  = (const float*)d_in[19];
    const float* emb_w   = (const float*)d_in[20];
    const float* emb_b   = (const float*)d_in[21];
    float* out = (float*)d_out;

    float *x1, *x2, *x3, *x, *xn, *cb, *hb;
    cudaGetSymbolAddress((void**)&x1, g_x1);
    cudaGetSymbolAddress((void**)&x2, g_x2);
    cudaGetSymbolAddress((void**)&x3, g_x3);
    cudaGetSymbolAddress((void**)&x,  g_x);
    cudaGetSymbolAddress((void**)&xn, g_xn);
    cudaGetSymbolAddress((void**)&cb, g_c);
    cudaGetSymbolAddress((void**)&hb, g_h);

    // conv stem: all three tensorized implicit GEMM
    conv1t_k<<<dim3(12, 1024), 256>>>(state, conv_w1, conv_b1, x1);
    convt_k<48, 60, 24, 30, 8><<<1024, 256>>>(x1, conv_w2, conv_b2, x2);
    convt_k<24, 30, 12, 15, 4><<<1024, 128>>>(x2, conv_w3, conv_b3, x3);

    // pre-projection + positional  (64x64 tiles, S=9, cp.async)
    gemm64_k<1><<<dim3(4, 16, 9), 256>>>(x3, pre_w, pre_b, pos_w, x,
                                         1024, 256, 2880, 9, 320);

    for (int k = 0; k < 4; k++) {
        ln_k<<<128, 256>>>(x, ln1_g + k * 256, ln1_b + k * 256, xn);
        gemm32_k<0><<<dim3(12, 32, 2), 256>>>(xn, enc_w + k * 256 * 768, enc_b + k * 768,
                                              nullptr, cb, 1024, 768, 256, 2, 128);
        attn_k<<<dim3(8, 16), 128>>>(cb, x);
        ln_k<<<128, 256>>>(x, ln2_g + k * 256, ln2_b + k * 256, x);
        gemm32_k<2><<<dim3(16, 32, 2), 256>>>(x, ffn_w1 + k * 256 * 1024, ffn_b1 + k * 1024,
                                              nullptr, hb, 1024, 1024, 256, 2, 128);
        gemm32_k<3><<<dim3(4, 32, 4), 256>>>(hb, ffn_w2 + k * 1024 * 256, ffn_b2 + k * 256,
                                             x, x, 1024, 256, 1024, 4, 256);
    }

    gemm32_k<0><<<dim3(4, 32, 4), 256>>>(x, emb_w, emb_b, nullptr, out,
                                         1024, 256, 256, 4, 64);

    reduce_k<<<256, 256>>>(out);
    norm_k<<<256, 256>>>(out);
}

// round 16
// speedup vs baseline: 1.3383x; 1.1537x over previous
#include <cuda_runtime.h>
#include <math.h>

// ---------------- scratch (device globals; no allocation allowed) ----------------
__device__ float g_x1[1024 * 16 * 48 * 60];   // conv1 out
__device__ float g_x2[1024 * 16 * 24 * 30];   // conv2 out
__device__ float g_x3[1024 * 16 * 12 * 15];   // conv3 out (= tokens x 2880)
__device__ float g_x [1024 * 256];            // residual stream
__device__ float g_xn[1024 * 256];            // ln1 output
__device__ float g_c [1024 * 768];            // qkv
__device__ float g_h [1024 * 1024];           // ffn hidden
__device__ float g_sp[4 * 1024 * 1024];       // split-K partials
__device__ unsigned g_cnt[512];               // per-tile arrival counters
__device__ double g_part[512];                // partial sums / sumsq

// ---------------- helpers ----------------
__device__ __forceinline__ unsigned f2tf(float f) {
    unsigned u;
    asm("cvt.rna.tf32.f32 %0, %1;" : "=r"(u) : "f"(f));
    return u;
}
__device__ __forceinline__ void mma_tf32(float c[4], unsigned a0, unsigned a1,
                                         unsigned a2, unsigned a3,
                                         unsigned b0, unsigned b1) {
    asm volatile(
        "mma.sync.aligned.m16n8k8.row.col.f32.tf32.tf32.f32 "
        "{%0,%1,%2,%3}, {%4,%5,%6,%7}, {%8,%9}, {%0,%1,%2,%3};\n"
        : "+f"(c[0]), "+f"(c[1]), "+f"(c[2]), "+f"(c[3])
        : "r"(a0), "r"(a1), "r"(a2), "r"(a3), "r"(b0), "r"(b1));
}
__device__ __forceinline__ void cpasync16(const void* smem_dst, const void* gsrc) {
    unsigned s = (unsigned)__cvta_generic_to_shared(smem_dst);
    asm volatile("cp.async.cg.shared.global [%0], [%1], 16;" :: "r"(s), "l"(gsrc));
}
__device__ __forceinline__ void cp_commit() {
    asm volatile("cp.async.commit_group;");
}
template <int N>
__device__ __forceinline__ void cp_wait() {
    asm volatile("cp.async.wait_group %0;" :: "n"(N));
}

// ---------------- conv1 tensorized: CIN=3, 96x120 -> 48x60, strip of 4 out rows --
__global__ void __launch_bounds__(256) conv1t_k(
    const float* __restrict__ in, const float* __restrict__ w,
    const float* __restrict__ bias, float* __restrict__ out) {
    constexpr int WS = 128, RS = 10, PLANE = RS * WS;
    constexpr int M = 240;                              // 4 out rows x 60
    __shared__ __align__(16) unsigned sIn[3 * PLANE];   // 3 ci planes
    __shared__ unsigned Bw[48 * 17];                    // weights [k][co]

    const int strip = blockIdx.x;        // 0..11
    const int n = blockIdx.y;            // image
    const int t = threadIdx.x;
    const int warp = t >> 5, lane = t & 31;
    const int g = lane >> 2, tig = lane & 3;

    const float* inp = in + (size_t)n * 3 * 96 * 120;
    for (int j = t; j < 900; j += 256) {
        int ci = j / 300, rem = j % 300;
        int r = rem / 30, chunk = rem % 30;
        int gih = strip * 8 + r - 1;
        if (gih >= 0 && gih < 96)
            cpasync16(&sIn[ci * PLANE + r * WS + 4 + chunk * 4],
                      inp + (ci * 96 + gih) * 120 + chunk * 4);
    }
    cp_commit();

    for (int i = t; i < 48 * 16; i += 256) {
        int co = i / 48, k = i % 48;
        Bw[k * 17 + co] = f2tf(w[i]);
    }
    for (int j = t; j < 60; j += 256) {
        int ci = j / 20, rem = j % 20;
        int r = rem >> 1, side = rem & 1;
        sIn[ci * PLANE + r * WS + (side ? 124 : 3)] = 0u;
    }
    if (strip == 0 || strip == 11) {
        int r = (strip == 0) ? 0 : 9;
        for (int j = t; j < 3 * 122; j += 256) {
            int ci = j / 122, cc = j % 122;
            sIn[ci * PLANE + r * WS + 3 + cc] = 0u;
        }
    }
    cp_wait<0>();
    __syncthreads();

    unsigned bf[6][2][2];
    #pragma unroll
    for (int kf = 0; kf < 6; kf++)
        #pragma unroll
        for (int nf = 0; nf < 2; nf++) {
            int kb = kf * 8 + tig;
            bf[kf][nf][0] = Bw[kb * 17 + nf * 8 + g];
            bf[kf][nf][1] = Bw[(kb + 4) * 17 + nf * 8 + g];
        }

    float acc[2][2][4];
    #pragma unroll
    for (int mt = 0; mt < 2; mt++)
        #pragma unroll
        for (int nf = 0; nf < 2; nf++)
            #pragma unroll
            for (int r = 0; r < 4; r++) acc[mt][nf][r] = 0.f;

    int rowoff[2][2];
    #pragma unroll
    for (int mt = 0; mt < 2; mt++)
        #pragma unroll
        for (int r = 0; r < 2; r++) {
            int m = (warp * 2 + mt) * 16 + g + r * 8;
            if (m >= M) m = M - 1;
            int ohl = m / 60, ow = m % 60;
            rowoff[mt][r] = (ohl * 2) * WS + ow * 2 + 3;
        }

    #pragma unroll
    for (int mt = 0; mt < 2; mt++) {
        #pragma unroll
        for (int kf = 0; kf < 6; kf++) {
            unsigned a[4];
            #pragma unroll
            for (int half = 0; half < 2; half++) {
                int k5 = kf * 8 + tig + half * 4;
                int ci = k5 >> 4, tap = k5 & 15;
                int off = ci * PLANE + (tap >> 2) * WS + (tap & 3);
                a[half * 2 + 0] = sIn[rowoff[mt][0] + off];
                a[half * 2 + 1] = sIn[rowoff[mt][1] + off];
            }
            #pragma unroll
            for (int nf = 0; nf < 2; nf++)
                mma_tf32(acc[mt][nf], a[0], a[1], a[2], a[3],
                         bf[kf][nf][0], bf[kf][nf][1]);
        }
    }

    #pragma unroll
    for (int mt = 0; mt < 2; mt++)
        #pragma unroll
        for (int r = 0; r < 2; r++) {
            int m = (warp * 2 + mt) * 16 + g + r * 8;
            if (m < M) {
                int oh = strip * 4 + m / 60, ow = m % 60;
                #pragma unroll
                for (int nf = 0; nf < 2; nf++) {
                    int co = nf * 8 + 2 * tig;
                    float v0 = acc[mt][nf][2 * r + 0] + __ldg(&bias[co]);
                    float v1 = acc[mt][nf][2 * r + 1] + __ldg(&bias[co + 1]);
                    out[((n * 16 + co) * 48 + oh) * 60 + ow] = fmaxf(v0, 0.f);
                    out[((n * 16 + co + 1) * 48 + oh) * 60 + ow] = fmaxf(v1, 0.f);
                }
            }
        }
}

// ---------------- tensorized conv (CIN=16, COUT=16, 4x4, stride2, pad1) --------
// Win%4==0: padded plane (interior at col 4), cp.async interior staging,
// borders zeroed once. Otherwise scalar staging (old layout).
template <int Hin, int Win, int Hout, int Wout, int NW>
__global__ void __launch_bounds__(NW * 32) convt_k(
    const float* __restrict__ in, const float* __restrict__ w,
    const float* __restrict__ bias, float* __restrict__ out) {
    constexpr bool ASY = (Win % 4 == 0);
    constexpr int IC = ASY ? 4 : 1;
    constexpr int HS = Hin + 2;
    constexpr int WS = ASY ? ((IC + Win + 1 + 3) & ~3) : (Win + 2);
    constexpr int PLANE = HS * WS;
    constexpr int M = Hout * Wout;
    constexpr int MT_TOT = (M + 15) / 16;
    constexpr int MT_PW = (MT_TOT + NW - 1) / NW;
    constexpr int NT = NW * 32;

    __shared__ __align__(16) unsigned sIn[2 * PLANE];
    __shared__ unsigned Bw[256 * 17];

    const int n = blockIdx.x;
    const int t = threadIdx.x;
    const int warp = t >> 5, lane = t & 31;
    const int g = lane >> 2, tig = lane & 3;

    for (int i = t; i < 256 * 16; i += NT) {
        int co = i >> 8, k = i & 255;
        Bw[k * 17 + co] = f2tf(w[i]);
    }
    if (ASY) {
        for (int j = t; j < 2 * PLANE; j += NT) sIn[j] = 0u;  // borders stay zero
    }

    int rowoff[MT_PW][2];
    #pragma unroll
    for (int mt = 0; mt < MT_PW; mt++) {
        #pragma unroll
        for (int r = 0; r < 2; r++) {
            int m = (warp * MT_PW + mt) * 16 + g + r * 8;
            if (m >= M) m = M - 1;
            int oh = m / Wout, ow = m % Wout;
            rowoff[mt][r] = (oh * 2) * WS + ow * 2 + (IC - 1);
        }
    }

    float acc[MT_PW][2][4];
    #pragma unroll
    for (int mt = 0; mt < MT_PW; mt++)
        #pragma unroll
        for (int nf = 0; nf < 2; nf++)
            #pragma unroll
            for (int r = 0; r < 4; r++) acc[mt][nf][r] = 0.f;

    const float* inp = in + (size_t)n * 16 * Hin * Win;

    #pragma unroll 1
    for (int cg = 0; cg < 8; cg++) {
        __syncthreads();
        if (ASY) {
            constexpr int CPR = Win / 4;        // 16B chunks per row
            for (int j = t; j < 2 * Hin * CPR; j += NT) {
                int ci_l = j / (Hin * CPR), rem = j % (Hin * CPR);
                int r = rem / CPR, chunk = rem % CPR;
                cpasync16(&sIn[ci_l * PLANE + (r + 1) * WS + IC + chunk * 4],
                          inp + ((cg * 2 + ci_l) * Hin + r) * Win + chunk * 4);
            }
            cp_commit();
            cp_wait<0>();
        } else {
            for (int j = t; j < 2 * PLANE; j += NT) {
                int ci_l = j / PLANE, rr = j % PLANE;
                int r = rr / WS, c = rr % WS;
                int gih = r - 1, giw = c - 1;
                float v = 0.f;
                if (gih >= 0 && gih < Hin && giw >= 0 && giw < Win)
                    v = inp[((cg * 2 + ci_l) * Hin + gih) * Win + giw];
                sIn[j] = f2tf(v);
            }
        }
        __syncthreads();

        unsigned bf[4][2][2];
        #pragma unroll
        for (int kf = 0; kf < 4; kf++)
            #pragma unroll
            for (int nf = 0; nf < 2; nf++) {
                int kb = cg * 32 + kf * 8 + tig;
                bf[kf][nf][0] = Bw[kb * 17 + nf * 8 + g];
                bf[kf][nf][1] = Bw[(kb + 4) * 17 + nf * 8 + g];
            }

        #pragma unroll
        for (int mt = 0; mt < MT_PW; mt++) {
            #pragma unroll
            for (int kf = 0; kf < 4; kf++) {
                unsigned a[4];
                #pragma unroll
                for (int half = 0; half < 2; half++) {
                    int k5 = kf * 8 + tig + half * 4;
                    int ci_l = k5 >> 4, tap = k5 & 15;
                    int off = ci_l * PLANE + (tap >> 2) * WS + (tap & 3);
                    a[half * 2 + 0] = sIn[rowoff[mt][0] + off];
                    a[half * 2 + 1] = sIn[rowoff[mt][1] + off];
                }
                #pragma unroll
                for (int nf = 0; nf < 2; nf++)
                    mma_tf32(acc[mt][nf], a[0], a[1], a[2], a[3],
                             bf[kf][nf][0], bf[kf][nf][1]);
            }
        }
    }

    #pragma unroll
    for (int mt = 0; mt < MT_PW; mt++) {
        #pragma unroll
        for (int r = 0; r < 2; r++) {
            int m = (warp * MT_PW + mt) * 16 + g + r * 8;
            if (m < M) {
                int oh = m / Wout, ow = m % Wout;
                #pragma unroll
                for (int nf = 0; nf < 2; nf++) {
                    int co = nf * 8 + 2 * tig;
                    float v0 = acc[mt][nf][2 * r + 0] + __ldg(&bias[co]);
                    float v1 = acc[mt][nf][2 * r + 1] + __ldg(&bias[co + 1]);
                    out[((n * 16 + co) * Hout + oh) * Wout + ow] = fmaxf(v0, 0.f);
                    out[((n * 16 + co + 1) * Hout + oh) * Wout + ow] = fmaxf(v1, 0.f);
                }
            }
        }
    }
}

template <int EPI>
__device__ __forceinline__ float epi_apply(float v, int m, int n, int N,
                                           const float* __restrict__ extra) {
    if (EPI == 1) v += extra[(m & 511) * N + n];
    if (EPI == 2) v = v * normcdff(v);
    if (EPI == 3) v += extra[m * N + n];
    return v;
}

// ---------------- GEMM A: 32x64 tile, 3-stage cp.async ring, 1 sync/chunk ------
template <int EPI>
__global__ void __launch_bounds__(256) gemm32_k(
    const float* __restrict__ A, const float* __restrict__ B,
    const float* __restrict__ bias, const float* __restrict__ extra,
    float* __restrict__ C, int M, int N, int K, int S, int Kc) {
    __shared__ __align__(16) unsigned As[3][32][36];
    __shared__ __align__(16) unsigned Bs[3][32][68];

    const int t = threadIdx.x;
    const int m0 = blockIdx.y * 32, n0 = blockIdx.x * 64;
    const int z = blockIdx.z;
    const int kb0 = z * Kc;
    const int warp = t >> 5, lane = t & 31;
    const int g = lane >> 2, tig = lane & 3;
    const int wm = (warp >> 2) * 16;
    const int wn = (warp & 3) * 16;

    float acc[2][4];
    #pragma unroll
    for (int nf = 0; nf < 2; nf++)
        #pragma unroll
        for (int r = 0; r < 4; r++) acc[nf][r] = 0.f;

    const int a_row = t >> 3, a_col = (t & 7) * 4;
    const int b_row = t >> 4, b_col = (t & 15) * 4;
    const int NC = Kc >> 5;
    const float* Ab = A + kb0 + (size_t)(m0 + a_row) * K + a_col;
    const float* Bb0 = B + (size_t)(kb0 + b_row) * N + n0 + b_col;
    const float* Bb1 = B + (size_t)(kb0 + b_row + 16) * N + n0 + b_col;

    // stage groups 0 and 1
    {
        cpasync16(&As[0][a_row][a_col], Ab);
        cpasync16(&Bs[0][b_row][b_col], Bb0);
        cpasync16(&Bs[0][b_row + 16][b_col], Bb1);
        cp_commit();
        if (NC > 1) {
            cpasync16(&As[1][a_row][a_col], Ab + 32);
            cpasync16(&Bs[1][b_row][b_col], Bb0 + (size_t)32 * N);
            cpasync16(&Bs[1][b_row + 16][b_col], Bb1 + (size_t)32 * N);
        }
        cp_commit();
    }

    for (int c = 0; c < NC; c++) {
        const int s = c % 3;
        cp_wait<1>();          // group c complete (c+1 may be pending)
        __syncthreads();       // all warps done reading stage (c+2)%3 (iter c-1)
        if (c + 2 < NC) {
            int k0 = (c + 2) * 32, st = (c + 2) % 3;
            cpasync16(&As[st][a_row][a_col], Ab + k0);
            cpasync16(&Bs[st][b_row][b_col], Bb0 + (size_t)k0 * N);
            cpasync16(&Bs[st][b_row + 16][b_col], Bb1 + (size_t)k0 * N);
        }
        cp_commit();

        #pragma unroll
        for (int ks = 0; ks < 4; ks++) {
            int k8 = ks * 8;
            unsigned a0 = As[s][wm + g][k8 + tig];
            unsigned a1 = As[s][wm + g + 8][k8 + tig];
            unsigned a2 = As[s][wm + g][k8 + tig + 4];
            unsigned a3 = As[s][wm + g + 8][k8 + tig + 4];
            #pragma unroll
            for (int nf = 0; nf < 2; nf++) {
                int nc = wn + nf * 8 + g;
                unsigned b0 = Bs[s][k8 + tig][nc];
                unsigned b1 = Bs[s][k8 + tig + 4][nc];
                mma_tf32(acc[nf], a0, a1, a2, a3, b0, b1);
            }
        }
    }

    if (S == 1) {
        #pragma unroll
        for (int half = 0; half < 2; half++) {
            int m = m0 + wm + g + half * 8;
            #pragma unroll
            for (int nf = 0; nf < 2; nf++) {
                int n = n0 + wn + nf * 8 + 2 * tig;
                float v0 = epi_apply<EPI>(acc[nf][2 * half] + bias[n], m, n, N, extra);
                float v1 = epi_apply<EPI>(acc[nf][2 * half + 1] + bias[n + 1], m, n + 1, N, extra);
                *(float2*)&C[m * N + n] = make_float2(v0, v1);
            }
        }
        return;
    }

    float* pz = g_sp + (size_t)z * M * N;
    #pragma unroll
    for (int half = 0; half < 2; half++) {
        int m = m0 + wm + g + half * 8;
        #pragma unroll
        for (int nf = 0; nf < 2; nf++) {
            int n = n0 + wn + nf * 8 + 2 * tig;
            *(float2*)&pz[m * N + n] = make_float2(acc[nf][2 * half], acc[nf][2 * half + 1]);
        }
    }
    __threadfence();
    __syncthreads();
    __shared__ unsigned s_old;
    const int tile = blockIdx.y * gridDim.x + blockIdx.x;
    if (t == 0) s_old = atomicAdd(&g_cnt[tile], 1);
    __syncthreads();
    if (s_old != (unsigned)(S - 1)) return;
    __threadfence();

    #pragma unroll
    for (int half = 0; half < 2; half++) {
        int m = m0 + wm + g + half * 8;
        #pragma unroll
        for (int nf = 0; nf < 2; nf++) {
            int n = n0 + wn + nf * 8 + 2 * tig;
            float v0 = bias[n], v1 = bias[n + 1];
            for (int s2 = 0; s2 < S; s2++) {
                float2 pv = *(const float2*)&g_sp[(size_t)s2 * M * N + m * N + n];
                v0 += pv.x; v1 += pv.y;
            }
            v0 = epi_apply<EPI>(v0, m, n, N, extra);
            v1 = epi_apply<EPI>(v1, m, n + 1, N, extra);
            *(float2*)&C[m * N + n] = make_float2(v0, v1);
        }
    }
    if (t == 0) g_cnt[tile] = 0;
}

// ---------------- GEMM B: 64x64 tile, 2-stage cp.async (SMEM-limited) ----------
template <int EPI>
__global__ void __launch_bounds__(256) gemm64_k(
    const float* __restrict__ A, const float* __restrict__ B,
    const float* __restrict__ bias, const float* __restrict__ extra,
    float* __restrict__ C, int M, int N, int K, int S, int Kc) {
    __shared__ __align__(16) unsigned As[2][64][36];
    __shared__ __align__(16) unsigned Bs[2][32][68];

    const int t = threadIdx.x;
    const int m0 = blockIdx.y * 64, n0 = blockIdx.x * 64;
    const int z = blockIdx.z;
    const int kb0 = z * Kc;
    const int warp = t >> 5, lane = t & 31;
    const int g = lane >> 2, tig = lane & 3;
    const int wm = (warp >> 2) * 32;
    const int wn = (warp & 3) * 16;

    float acc[2][2][4];
    #pragma unroll
    for (int mt = 0; mt < 2; mt++)
        #pragma unroll
        for (int nf = 0; nf < 2; nf++)
            #pragma unroll
            for (int r = 0; r < 4; r++) acc[mt][nf][r] = 0.f;

    const int a_row = t >> 2, a_colb = (t & 3) * 8;
    const int b_row = t >> 3, b_colb = (t & 7) * 8;
    const int NC = Kc >> 5;
    const float* Ab = A + kb0 + (size_t)(m0 + a_row) * K + a_colb;
    const float* Bb = B + (size_t)(kb0 + b_row) * N + n0 + b_colb;

    cpasync16(&As[0][a_row][a_colb], Ab);
    cpasync16(&As[0][a_row][a_colb + 4], Ab + 4);
    cpasync16(&Bs[0][b_row][b_colb], Bb);
    cpasync16(&Bs[0][b_row][b_colb + 4], Bb + 4);
    cp_commit();

    for (int c = 0; c < NC; c++) {
        const int s = c & 1;
        if (c + 1 < NC) {
            int k0 = (c + 1) * 32;
            cpasync16(&As[s ^ 1][a_row][a_colb], Ab + k0);
            cpasync16(&As[s ^ 1][a_row][a_colb + 4], Ab + k0 + 4);
            cpasync16(&Bs[s ^ 1][b_row][b_colb], Bb + (size_t)k0 * N);
            cpasync16(&Bs[s ^ 1][b_row][b_colb + 4], Bb + (size_t)k0 * N + 4);
        }
        cp_commit();
        cp_wait<1>();
        __syncthreads();

        #pragma unroll
        for (int ks = 0; ks < 4; ks++) {
            const int k8 = ks * 8;
            unsigned a[2][4], bf[2][2];
            #pragma unroll
            for (int mt = 0; mt < 2; mt++) {
                int mr = wm + mt * 16 + g;
                a[mt][0] = As[s][mr][k8 + tig];
                a[mt][1] = As[s][mr + 8][k8 + tig];
                a[mt][2] = As[s][mr][k8 + tig + 4];
                a[mt][3] = As[s][mr + 8][k8 + tig + 4];
            }
            #pragma unroll
            for (int nf = 0; nf < 2; nf++) {
                int nc = wn + nf * 8 + g;
                bf[nf][0] = Bs[s][k8 + tig][nc];
                bf[nf][1] = Bs[s][k8 + tig + 4][nc];
            }
            #pragma unroll
            for (int mt = 0; mt < 2; mt++)
                #pragma unroll
                for (int nf = 0; nf < 2; nf++)
                    mma_tf32(acc[mt][nf], a[mt][0], a[mt][1], a[mt][2], a[mt][3],
                             bf[nf][0], bf[nf][1]);
        }
        __syncthreads();
    }

    if (S == 1) {
        #pragma unroll
        for (int mt = 0; mt < 2; mt++)
            #pragma unroll
            for (int half = 0; half < 2; half++) {
                int m = m0 + wm + mt * 16 + g + half * 8;
                #pragma unroll
                for (int nf = 0; nf < 2; nf++) {
                    int n = n0 + wn + nf * 8 + 2 * tig;
                    float v0 = epi_apply<EPI>(acc[mt][nf][2 * half] + bias[n], m, n, N, extra);
                    float v1 = epi_apply<EPI>(acc[mt][nf][2 * half + 1] + bias[n + 1], m, n + 1, N, extra);
                    *(float2*)&C[m * N + n] = make_float2(v0, v1);
                }
            }
        return;
    }

    float* pz = g_sp + (size_t)z * M * N;
    #pragma unroll
    for (int mt = 0; mt < 2; mt++)
        #pragma unroll
        for (int half = 0; half < 2; half++) {
            int m = m0 + wm + mt * 16 + g + half * 8;
            #pragma unroll
            for (int nf = 0; nf < 2; nf++) {
                int n = n0 + wn + nf * 8 + 2 * tig;
                *(float2*)&pz[m * N + n] =
                    make_float2(acc[mt][nf][2 * half], acc[mt][nf][2 * half + 1]);
            }
        }
    __threadfence();
    __syncthreads();
    __shared__ unsigned s_old;
    const int tile = blockIdx.y * gridDim.x + blockIdx.x;
    if (t == 0) s_old = atomicAdd(&g_cnt[tile], 1);
    __syncthreads();
    if (s_old != (unsigned)(S - 1)) return;
    __threadfence();

    #pragma unroll
    for (int mt = 0; mt < 2; mt++)
        #pragma unroll
        for (int half = 0; half < 2; half++) {
            int m = m0 + wm + mt * 16 + g + half * 8;
            #pragma unroll
            for (int nf = 0; nf < 2; nf++) {
                int n = n0 + wn + nf * 8 + 2 * tig;
                float v0 = bias[n], v1 = bias[n + 1];
                for (int s2 = 0; s2 < S; s2++) {
                    float2 pv = *(const float2*)&g_sp[(size_t)s2 * M * N + m * N + n];
                    v0 += pv.x; v1 += pv.y;
                }
                v0 = epi_apply<EPI>(v0, m, n, N, extra);
                v1 = epi_apply<EPI>(v1, m, n + 1, N, extra);
                *(float2*)&C[m * N + n] = make_float2(v0, v1);
            }
        }
    if (t == 0) g_cnt[tile] = 0;
}

// ---------------- layernorm: one warp per row, shuffle reductions ----------------
__global__ void __launch_bounds__(256) ln_k(
    const float* __restrict__ in, const float* __restrict__ gw,
    const float* __restrict__ bw, float* __restrict__ out) {
    const int t = threadIdx.x, warp = t >> 5, lane = t & 31;
    const int row = blockIdx.x * 8 + warp;
    const float4* r = (const float4*)(in + row * 256);
    float4 v0 = r[lane], v1 = r[lane + 32];
    float s = v0.x + v0.y + v0.z + v0.w + v1.x + v1.y + v1.z + v1.w;
    #pragma unroll
    for (int o = 16; o > 0; o >>= 1) s += __shfl_xor_sync(0xffffffffu, s, o);
    float mu = s * (1.f / 256.f);
    float d0x = v0.x - mu, d0y = v0.y - mu, d0z = v0.z - mu, d0w = v0.w - mu;
    float d1x = v1.x - mu, d1y = v1.y - mu, d1z = v1.z - mu, d1w = v1.w - mu;
    float ss = d0x * d0x + d0y * d0y + d0z * d0z + d0w * d0w
             + d1x * d1x + d1y * d1y + d1z * d1z + d1w * d1w;
    #pragma unroll
    for (int o = 16; o > 0; o >>= 1) ss += __shfl_xor_sync(0xffffffffu, ss, o);
    float inv = rsqrtf(ss * (1.f / 256.f) + 1e-5f);
    const float4* g4 = (const float4*)gw;
    const float4* b4 = (const float4*)bw;
    float4 ga = g4[lane], gb = g4[lane + 32];
    float4 ba = b4[lane], bb = b4[lane + 32];
    float4* o4 = (float4*)(out + row * 256);
    o4[lane] = make_float4(d0x * inv * ga.x + ba.x, d0y * inv * ga.y + ba.y,
                           d0z * inv * ga.z + ba.z, d0w * inv * ga.w + ba.w);
    o4[lane + 32] = make_float4(d1x * inv * gb.x + bb.x, d1y * inv * gb.y + bb.y,
                                d1z * inv * gb.z + bb.z, d1w * inv * gb.w + bb.w);
}

// ---------------- causal attention: 2 threads/query, 3-stage ring, 1 sync/tile --
__global__ void __launch_bounds__(128) attn_k(const float* __restrict__ c,
                                              float* __restrict__ x) {
    __shared__ __align__(16) float Ks[3][32][32];
    __shared__ __align__(16) float Vs[3][32][32];
    const int t = threadIdx.x;            // 128 threads
    const int qt = blockIdx.x;            // 8 query tiles of 64
    const int bh = blockIdx.y;            // 16 (b,h)
    const int b = bh >> 3, h = bh & 7;
    const int qi = qt * 64 + (t & 63);
    const int dhalf = t >> 6;             // 0 or 1: V dims [dhalf*16, +16)
    const float* crow = c + (b * 512 + qi) * 768 + h * 32;

    const float SC = 0.17677669529663687f;  // 1/sqrt(32)
    float q[32];
    #pragma unroll
    for (int d4 = 0; d4 < 8; d4++) {
        float4 qv = *(const float4*)(crow + d4 * 4);
        q[4 * d4 + 0] = qv.x * SC;
        q[4 * d4 + 1] = qv.y * SC;
        q[4 * d4 + 2] = qv.z * SC;
        q[4 * d4 + 3] = qv.w * SC;
    }
    float acc[16];
    #pragma unroll
    for (int d = 0; d < 16; d++) acc[d] = 0.f;
    float mrun = -1e30f, l = 0.f;

    const int ntiles = qt * 2 + 2;        // covers kb = 0..qt*64+32
    const int jj = t >> 2, q8 = (t & 3) * 8;
    const float* kvbase = c + ((size_t)b * 512 + jj) * 768 + 256 + h * 32 + q8;

    // prologue: tiles 0 and 1
    cpasync16(&Ks[0][jj][q8], kvbase);
    cpasync16(&Ks[0][jj][q8 + 4], kvbase + 4);
    cpasync16(&Vs[0][jj][q8], kvbase + 256);
    cpasync16(&Vs[0][jj][q8 + 4], kvbase + 260);
    cp_commit();
    if (ntiles > 1) {
        const float* kr = kvbase + (size_t)32 * 768;
        cpasync16(&Ks[1][jj][q8], kr);
        cpasync16(&Ks[1][jj][q8 + 4], kr + 4);
        cpasync16(&Vs[1][jj][q8], kr + 256);
        cpasync16(&Vs[1][jj][q8 + 4], kr + 260);
    }
    cp_commit();

    for (int ti = 0; ti < ntiles; ti++) {
        const int s = ti % 3;
        cp_wait<1>();
        __syncthreads();
        if (ti + 2 < ntiles) {
            const int st = (ti + 2) % 3;
            const float* kr = kvbase + (size_t)(ti + 2) * 32 * 768;
            cpasync16(&Ks[st][jj][q8], kr);
            cpasync16(&Ks[st][jj][q8 + 4], kr + 4);
            cpasync16(&Vs[st][jj][q8], kr + 256);
            cpasync16(&Vs[st][jj][q8 + 4], kr + 260);
        }
        cp_commit();

        const int kb = ti * 32;
        if (kb <= qi) {
            int jmax = qi - kb;
            if (jmax > 31) jmax = 31;
            float sarr[32];
            float tmax = -1e30f;
            #pragma unroll
            for (int j = 0; j < 32; j++) {
                if (j <= jmax) {
                    float sc = 0.f;
                    #pragma unroll
                    for (int d = 0; d < 32; d++) sc += q[d] * Ks[s][j][d];
                    sarr[j] = sc;
                    tmax = fmaxf(tmax, sc);
                }
            }
            float newm = fmaxf(mrun, tmax);
            float alpha = __expf(mrun - newm);
            l *= alpha;
            #pragma unroll
            for (int d = 0; d < 16; d++) acc[d] *= alpha;
            #pragma unroll
            for (int j = 0; j < 32; j++) {
                if (j <= jmax) {
                    float p = __expf(sarr[j] - newm);
                    l += p;
                    #pragma unroll
                    for (int d = 0; d < 16; d++) acc[d] += p * Vs[s][j][dhalf * 16 + d];
                }
            }
            mrun = newm;
        }
    }
    float inv = 1.f / l;
    float* xr = x + (b * 512 + qi) * 256 + h * 32 + dhalf * 16;
    #pragma unroll
    for (int d = 0; d < 16; d++) xr[d] += acc[d] * inv;
}

// ---------------- deterministic global mean/std (ddof=1) + normalize ------------
__global__ void reduce_k(const float* __restrict__ e) {
    __shared__ double s1[256], s2[256];
    const int t = threadIdx.x;
    double s = 0.0, ss = 0.0;
    for (int i = blockIdx.x * 256 + t; i < 262144; i += 256 * 256) {
        double v = (double)e[i];
        s += v;
        ss += v * v;
    }
    s1[t] = s;
    s2[t] = ss;
    __syncthreads();
    for (int k = 128; k > 0; k >>= 1) {
        if (t < k) { s1[t] += s1[t + k]; s2[t] += s2[t + k]; }
        __syncthreads();
    }
    if (t == 0) { g_part[blockIdx.x] = s1[0]; g_part[256 + blockIdx.x] = s2[0]; }
}

__global__ void norm_k(float* e) {
    __shared__ double s1[256], s2[256];
    const int t = threadIdx.x;
    s1[t] = g_part[t];
    s2[t] = g_part[256 + t];
    __syncthreads();
    for (int k = 128; k > 0; k >>= 1) {
        if (t < k) { s1[t] += s1[t + k]; s2[t] += s2[t + k]; }
        __syncthreads();
    }
    const double n = 262144.0;
    double mu = s1[0] / n;
    double var = (s2[0] - n * mu * mu) / (n - 1.0);
    float inv = (float)(1.0 / sqrt(var));
    float fmu = (float)mu;
    int i = (blockIdx.x * 256 + t) * 4;
    float4 v = *(float4*)&e[i];
    v.x = (v.x - fmu) * inv + 1e-10f;
    v.y = (v.y - fmu) * inv + 1e-10f;
    v.z = (v.z - fmu) * inv + 1e-10f;
    v.w = (v.w - fmu) * inv + 1e-10f;
    *(float4*)&e[i] = v;
}

// ---------------- launch ----------------
extern "C" void kernel_launch(void* const* d_in, const int* in_sizes, int n_in,
                              void* d_out, int out_size) {
    const float* state   = (const float*)d_in[0];
    const float* conv_w1 = (const float*)d_in[1];
    const float* conv_b1 = (const float*)d_in[2];
    const float* conv_w2 = (const float*)d_in[3];
    const float* conv_b2 = (const float*)d_in[4];
    const float* conv_w3 = (const float*)d_in[5];
    const float* conv_b3 = (const float*)d_in[6];
    const float* pre_w   = (const float*)d_in[7];
    const float* pre_b   = (const float*)d_in[8];
    const float* pos_w   = (const float*)d_in[9];
    const float* ln1_g   = (const float*)d_in[10];
    const float* ln1_b   = (const float*)d_in[11];
    const float* enc_w   = (const float*)d_in[12];
    const float* enc_b   = (const float*)d_in[13];
    const float* ln2_g   = (const float*)d_in[14];
    const float* ln2_b   = (const float*)d_in[15];
    const float* ffn_w1  = (const float*)d_in[16];
    const float* ffn_b1  = (const float*)d_in[17];
    const float* ffn_w2  = (const float*)d_in[18];
    const float* ffn_b2  = (const float*)d_in[19];
    const float* emb_w   = (const float*)d_in[20];
    const float* emb_b   = (const float*)d_in[21];
    float* out = (float*)d_out;

    float *x1, *x2, *x3, *x, *xn, *cb, *hb;
    cudaGetSymbolAddress((void**)&x1, g_x1);
    cudaGetSymbolAddress((void**)&x2, g_x2);
    cudaGetSymbolAddress((void**)&x3, g_x3);
    cudaGetSymbolAddress((void**)&x,  g_x);
    cudaGetSymbolAddress((void**)&xn, g_xn);
    cudaGetSymbolAddress((void**)&cb, g_c);
    cudaGetSymbolAddress((void**)&hb, g_h);

    // conv stem: all three tensorized implicit GEMM
    conv1t_k<<<dim3(12, 1024), 256>>>(state, conv_w1, conv_b1, x1);
    convt_k<48, 60, 24, 30, 8><<<1024, 256>>>(x1, conv_w2, conv_b2, x2);
    convt_k<24, 30, 12, 15, 4><<<1024, 128>>>(x2, conv_w3, conv_b3, x3);

    // pre-projection + positional  (64x64 tiles, S=9, cp.async)
    gemm64_k<1><<<dim3(4, 16, 9), 256>>>(x3, pre_w, pre_b, pos_w, x,
                                         1024, 256, 2880, 9, 320);

    for (int k = 0; k < 4; k++) {
        ln_k<<<128, 256>>>(x, ln1_g + k * 256, ln1_b + k * 256, xn);
        gemm32_k<0><<<dim3(12, 32, 2), 256>>>(xn, enc_w + k * 256 * 768, enc_b + k * 768,
                                              nullptr, cb, 1024, 768, 256, 2, 128);
        attn_k<<<dim3(8, 16), 128>>>(cb, x);
        ln_k<<<128, 256>>>(x, ln2_g + k * 256, ln2_b + k * 256, x);
        gemm32_k<2><<<dim3(16, 32, 2), 256>>>(x, ffn_w1 + k * 256 * 1024, ffn_b1 + k * 1024,
                                              nullptr, hb, 1024, 1024, 256, 2, 128);
        gemm32_k<3><<<dim3(4, 32, 4), 256>>>(hb, ffn_w2 + k * 1024 * 256, ffn_b2 + k * 256,
                                             x, x, 1024, 256, 1024, 4, 256);
    }

    gemm32_k<0><<<dim3(4, 32, 4), 256>>>(x, emb_w, emb_b, nullptr, out,
                                         1024, 256, 256, 4, 64);

    reduce_k<<<256, 256>>>(out);
    norm_k<<<256, 256>>>(out);
}

// round 17
// speedup vs baseline: 1.3404x; 1.0015x over previous
#include <cuda_runtime.h>
#include <math.h>

// ---------------- scratch (device globals; no allocation allowed) ----------------
__device__ float g_x1[1024 * 16 * 48 * 60];   // conv1 out
__device__ float g_x2[1024 * 16 * 24 * 30];   // conv2 out
__device__ float g_x3[1024 * 16 * 12 * 15];   // conv3 out (= tokens x 2880)
__device__ float g_x [1024 * 256];            // residual stream
__device__ float g_xn[1024 * 256];            // ln1 output
__device__ float g_c [1024 * 768];            // qkv
__device__ float g_h [1024 * 1024];           // ffn hidden
__device__ float g_sp[4 * 1024 * 1024];       // split-K partials
__device__ unsigned g_cnt[512];               // per-tile arrival counters
__device__ double g_part[512];                // partial sums / sumsq

// ---------------- helpers ----------------
__device__ __forceinline__ unsigned f2tf(float f) {
    unsigned u;
    asm("cvt.rna.tf32.f32 %0, %1;" : "=r"(u) : "f"(f));
    return u;
}
__device__ __forceinline__ void mma_tf32(float c[4], unsigned a0, unsigned a1,
                                         unsigned a2, unsigned a3,
                                         unsigned b0, unsigned b1) {
    asm volatile(
        "mma.sync.aligned.m16n8k8.row.col.f32.tf32.tf32.f32 "
        "{%0,%1,%2,%3}, {%4,%5,%6,%7}, {%8,%9}, {%0,%1,%2,%3};\n"
        : "+f"(c[0]), "+f"(c[1]), "+f"(c[2]), "+f"(c[3])
        : "r"(a0), "r"(a1), "r"(a2), "r"(a3), "r"(b0), "r"(b1));
}
__device__ __forceinline__ void cpasync16(const void* smem_dst, const void* gsrc) {
    unsigned s = (unsigned)__cvta_generic_to_shared(smem_dst);
    asm volatile("cp.async.cg.shared.global [%0], [%1], 16;" :: "r"(s), "l"(gsrc));
}
__device__ __forceinline__ void cp_commit() {
    asm volatile("cp.async.commit_group;");
}
template <int N>
__device__ __forceinline__ void cp_wait() {
    asm volatile("cp.async.wait_group %0;" :: "n"(N));
}

// ---------------- conv1 tensorized: CIN=3, 96x120 -> 48x60, strip of 4 out rows --
__global__ void __launch_bounds__(256) conv1t_k(
    const float* __restrict__ in, const float* __restrict__ w,
    const float* __restrict__ bias, float* __restrict__ out) {
    constexpr int WS = 128, RS = 10, PLANE = RS * WS;
    constexpr int M = 240;                              // 4 out rows x 60
    __shared__ __align__(16) unsigned sIn[3 * PLANE];   // 3 ci planes
    __shared__ unsigned Bw[48 * 17];                    // weights [k][co]

    const int strip = blockIdx.x;        // 0..11
    const int n = blockIdx.y;            // image
    const int t = threadIdx.x;
    const int warp = t >> 5, lane = t & 31;
    const int g = lane >> 2, tig = lane & 3;

    const float* inp = in + (size_t)n * 3 * 96 * 120;
    for (int j = t; j < 900; j += 256) {
        int ci = j / 300, rem = j % 300;
        int r = rem / 30, chunk = rem % 30;
        int gih = strip * 8 + r - 1;
        if (gih >= 0 && gih < 96)
            cpasync16(&sIn[ci * PLANE + r * WS + 4 + chunk * 4],
                      inp + (ci * 96 + gih) * 120 + chunk * 4);
    }
    cp_commit();

    for (int i = t; i < 48 * 16; i += 256) {
        int co = i / 48, k = i % 48;
        Bw[k * 17 + co] = f2tf(w[i]);
    }
    for (int j = t; j < 60; j += 256) {
        int ci = j / 20, rem = j % 20;
        int r = rem >> 1, side = rem & 1;
        sIn[ci * PLANE + r * WS + (side ? 124 : 3)] = 0u;
    }
    if (strip == 0 || strip == 11) {
        int r = (strip == 0) ? 0 : 9;
        for (int j = t; j < 3 * 122; j += 256) {
            int ci = j / 122, cc = j % 122;
            sIn[ci * PLANE + r * WS + 3 + cc] = 0u;
        }
    }
    cp_wait<0>();
    __syncthreads();

    unsigned bf[6][2][2];
    #pragma unroll
    for (int kf = 0; kf < 6; kf++)
        #pragma unroll
        for (int nf = 0; nf < 2; nf++) {
            int kb = kf * 8 + tig;
            bf[kf][nf][0] = Bw[kb * 17 + nf * 8 + g];
            bf[kf][nf][1] = Bw[(kb + 4) * 17 + nf * 8 + g];
        }

    float acc[2][2][4];
    #pragma unroll
    for (int mt = 0; mt < 2; mt++)
        #pragma unroll
        for (int nf = 0; nf < 2; nf++)
            #pragma unroll
            for (int r = 0; r < 4; r++) acc[mt][nf][r] = 0.f;

    int rowoff[2][2];
    #pragma unroll
    for (int mt = 0; mt < 2; mt++)
        #pragma unroll
        for (int r = 0; r < 2; r++) {
            int m = (warp * 2 + mt) * 16 + g + r * 8;
            if (m >= M) m = M - 1;
            int ohl = m / 60, ow = m % 60;
            rowoff[mt][r] = (ohl * 2) * WS + ow * 2 + 3;
        }

    #pragma unroll
    for (int mt = 0; mt < 2; mt++) {
        #pragma unroll
        for (int kf = 0; kf < 6; kf++) {
            unsigned a[4];
            #pragma unroll
            for (int half = 0; half < 2; half++) {
                int k5 = kf * 8 + tig + half * 4;
                int ci = k5 >> 4, tap = k5 & 15;
                int off = ci * PLANE + (tap >> 2) * WS + (tap & 3);
                a[half * 2 + 0] = sIn[rowoff[mt][0] + off];
                a[half * 2 + 1] = sIn[rowoff[mt][1] + off];
            }
            #pragma unroll
            for (int nf = 0; nf < 2; nf++)
                mma_tf32(acc[mt][nf], a[0], a[1], a[2], a[3],
                         bf[kf][nf][0], bf[kf][nf][1]);
        }
    }

    #pragma unroll
    for (int mt = 0; mt < 2; mt++)
        #pragma unroll
        for (int r = 0; r < 2; r++) {
            int m = (warp * 2 + mt) * 16 + g + r * 8;
            if (m < M) {
                int oh = strip * 4 + m / 60, ow = m % 60;
                #pragma unroll
                for (int nf = 0; nf < 2; nf++) {
                    int co = nf * 8 + 2 * tig;
                    float v0 = acc[mt][nf][2 * r + 0] + __ldg(&bias[co]);
                    float v1 = acc[mt][nf][2 * r + 1] + __ldg(&bias[co + 1]);
                    out[((n * 16 + co) * 48 + oh) * 60 + ow] = fmaxf(v0, 0.f);
                    out[((n * 16 + co + 1) * 48 + oh) * 60 + ow] = fmaxf(v1, 0.f);
                }
            }
        }
}

// ---------------- tensorized conv (CIN=16, COUT=16, 4x4, stride2, pad1) --------
// Win%4==0: padded plane (interior at col 4), cp.async interior staging,
// borders zeroed once. Otherwise scalar staging (old layout).
template <int Hin, int Win, int Hout, int Wout, int NW>
__global__ void __launch_bounds__(NW * 32) convt_k(
    const float* __restrict__ in, const float* __restrict__ w,
    const float* __restrict__ bias, float* __restrict__ out) {
    constexpr bool ASY = (Win % 4 == 0);
    constexpr int IC = ASY ? 4 : 1;
    constexpr int HS = Hin + 2;
    constexpr int WS = ASY ? ((IC + Win + 1 + 3) & ~3) : (Win + 2);
    constexpr int PLANE = HS * WS;
    constexpr int M = Hout * Wout;
    constexpr int MT_TOT = (M + 15) / 16;
    constexpr int MT_PW = (MT_TOT + NW - 1) / NW;
    constexpr int NT = NW * 32;

    __shared__ __align__(16) unsigned sIn[2 * PLANE];
    __shared__ unsigned Bw[256 * 17];

    const int n = blockIdx.x;
    const int t = threadIdx.x;
    const int warp = t >> 5, lane = t & 31;
    const int g = lane >> 2, tig = lane & 3;

    for (int i = t; i < 256 * 16; i += NT) {
        int co = i >> 8, k = i & 255;
        Bw[k * 17 + co] = f2tf(w[i]);
    }
    if (ASY) {
        for (int j = t; j < 2 * PLANE; j += NT) sIn[j] = 0u;  // borders stay zero
    }

    int rowoff[MT_PW][2];
    #pragma unroll
    for (int mt = 0; mt < MT_PW; mt++) {
        #pragma unroll
        for (int r = 0; r < 2; r++) {
            int m = (warp * MT_PW + mt) * 16 + g + r * 8;
            if (m >= M) m = M - 1;
            int oh = m / Wout, ow = m % Wout;
            rowoff[mt][r] = (oh * 2) * WS + ow * 2 + (IC - 1);
        }
    }

    float acc[MT_PW][2][4];
    #pragma unroll
    for (int mt = 0; mt < MT_PW; mt++)
        #pragma unroll
        for (int nf = 0; nf < 2; nf++)
            #pragma unroll
            for (int r = 0; r < 4; r++) acc[mt][nf][r] = 0.f;

    const float* inp = in + (size_t)n * 16 * Hin * Win;

    #pragma unroll 1
    for (int cg = 0; cg < 8; cg++) {
        __syncthreads();
        if (ASY) {
            constexpr int CPR = Win / 4;        // 16B chunks per row
            for (int j = t; j < 2 * Hin * CPR; j += NT) {
                int ci_l = j / (Hin * CPR), rem = j % (Hin * CPR);
                int r = rem / CPR, chunk = rem % CPR;
                cpasync16(&sIn[ci_l * PLANE + (r + 1) * WS + IC + chunk * 4],
                          inp + ((cg * 2 + ci_l) * Hin + r) * Win + chunk * 4);
            }
            cp_commit();
            cp_wait<0>();
        } else {
            for (int j = t; j < 2 * PLANE; j += NT) {
                int ci_l = j / PLANE, rr = j % PLANE;
                int r = rr / WS, c = rr % WS;
                int gih = r - 1, giw = c - 1;
                float v = 0.f;
                if (gih >= 0 && gih < Hin && giw >= 0 && giw < Win)
                    v = inp[((cg * 2 + ci_l) * Hin + gih) * Win + giw];
                sIn[j] = f2tf(v);
            }
        }
        __syncthreads();

        unsigned bf[4][2][2];
        #pragma unroll
        for (int kf = 0; kf < 4; kf++)
            #pragma unroll
            for (int nf = 0; nf < 2; nf++) {
                int kb = cg * 32 + kf * 8 + tig;
                bf[kf][nf][0] = Bw[kb * 17 + nf * 8 + g];
                bf[kf][nf][1] = Bw[(kb + 4) * 17 + nf * 8 + g];
            }

        #pragma unroll
        for (int mt = 0; mt < MT_PW; mt++) {
            #pragma unroll
            for (int kf = 0; kf < 4; kf++) {
                unsigned a[4];
                #pragma unroll
                for (int half = 0; half < 2; half++) {
                    int k5 = kf * 8 + tig + half * 4;
                    int ci_l = k5 >> 4, tap = k5 & 15;
                    int off = ci_l * PLANE + (tap >> 2) * WS + (tap & 3);
                    a[half * 2 + 0] = sIn[rowoff[mt][0] + off];
                    a[half * 2 + 1] = sIn[rowoff[mt][1] + off];
                }
                #pragma unroll
                for (int nf = 0; nf < 2; nf++)
                    mma_tf32(acc[mt][nf], a[0], a[1], a[2], a[3],
                             bf[kf][nf][0], bf[kf][nf][1]);
            }
        }
    }

    #pragma unroll
    for (int mt = 0; mt < MT_PW; mt++) {
        #pragma unroll
        for (int r = 0; r < 2; r++) {
            int m = (warp * MT_PW + mt) * 16 + g + r * 8;
            if (m < M) {
                int oh = m / Wout, ow = m % Wout;
                #pragma unroll
                for (int nf = 0; nf < 2; nf++) {
                    int co = nf * 8 + 2 * tig;
                    float v0 = acc[mt][nf][2 * r + 0] + __ldg(&bias[co]);
                    float v1 = acc[mt][nf][2 * r + 1] + __ldg(&bias[co + 1]);
                    out[((n * 16 + co) * Hout + oh) * Wout + ow] = fmaxf(v0, 0.f);
                    out[((n * 16 + co + 1) * Hout + oh) * Wout + ow] = fmaxf(v1, 0.f);
                }
            }
        }
    }
}

template <int EPI>
__device__ __forceinline__ float epi_apply(float v, int m, int n, int N,
                                           const float* __restrict__ extra) {
    if (EPI == 1) v += extra[(m & 511) * N + n];
    if (EPI == 2) v = v * normcdff(v);
    if (EPI == 3) v += extra[m * N + n];
    return v;
}

// ---------------- GEMM A: 32x64 tile, 3-stage cp.async ring, 1 sync/chunk ------
template <int EPI>
__global__ void __launch_bounds__(256) gemm32_k(
    const float* __restrict__ A, const float* __restrict__ B,
    const float* __restrict__ bias, const float* __restrict__ extra,
    float* __restrict__ C, int M, int N, int K, int S, int Kc) {
    __shared__ __align__(16) unsigned As[3][32][36];
    __shared__ __align__(16) unsigned Bs[3][32][68];

    const int t = threadIdx.x;
    const int m0 = blockIdx.y * 32, n0 = blockIdx.x * 64;
    const int z = blockIdx.z;
    const int kb0 = z * Kc;
    const int warp = t >> 5, lane = t & 31;
    const int g = lane >> 2, tig = lane & 3;
    const int wm = (warp >> 2) * 16;
    const int wn = (warp & 3) * 16;

    float acc[2][4];
    #pragma unroll
    for (int nf = 0; nf < 2; nf++)
        #pragma unroll
        for (int r = 0; r < 4; r++) acc[nf][r] = 0.f;

    const int a_row = t >> 3, a_col = (t & 7) * 4;
    const int b_row = t >> 4, b_col = (t & 15) * 4;
    const int NC = Kc >> 5;
    const float* Ab = A + kb0 + (size_t)(m0 + a_row) * K + a_col;
    const float* Bb0 = B + (size_t)(kb0 + b_row) * N + n0 + b_col;
    const float* Bb1 = B + (size_t)(kb0 + b_row + 16) * N + n0 + b_col;

    // stage groups 0 and 1
    {
        cpasync16(&As[0][a_row][a_col], Ab);
        cpasync16(&Bs[0][b_row][b_col], Bb0);
        cpasync16(&Bs[0][b_row + 16][b_col], Bb1);
        cp_commit();
        if (NC > 1) {
            cpasync16(&As[1][a_row][a_col], Ab + 32);
            cpasync16(&Bs[1][b_row][b_col], Bb0 + (size_t)32 * N);
            cpasync16(&Bs[1][b_row + 16][b_col], Bb1 + (size_t)32 * N);
        }
        cp_commit();
    }

    for (int c = 0; c < NC; c++) {
        const int s = c % 3;
        cp_wait<1>();          // group c complete (c+1 may be pending)
        __syncthreads();       // all warps done reading stage (c+2)%3 (iter c-1)
        if (c + 2 < NC) {
            int k0 = (c + 2) * 32, st = (c + 2) % 3;
            cpasync16(&As[st][a_row][a_col], Ab + k0);
            cpasync16(&Bs[st][b_row][b_col], Bb0 + (size_t)k0 * N);
            cpasync16(&Bs[st][b_row + 16][b_col], Bb1 + (size_t)k0 * N);
        }
        cp_commit();

        #pragma unroll
        for (int ks = 0; ks < 4; ks++) {
            int k8 = ks * 8;
            unsigned a0 = As[s][wm + g][k8 + tig];
            unsigned a1 = As[s][wm + g + 8][k8 + tig];
            unsigned a2 = As[s][wm + g][k8 + tig + 4];
            unsigned a3 = As[s][wm + g + 8][k8 + tig + 4];
            #pragma unroll
            for (int nf = 0; nf < 2; nf++) {
                int nc = wn + nf * 8 + g;
                unsigned b0 = Bs[s][k8 + tig][nc];
                unsigned b1 = Bs[s][k8 + tig + 4][nc];
                mma_tf32(acc[nf], a0, a1, a2, a3, b0, b1);
            }
        }
    }

    if (S == 1) {
        #pragma unroll
        for (int half = 0; half < 2; half++) {
            int m = m0 + wm + g + half * 8;
            #pragma unroll
            for (int nf = 0; nf < 2; nf++) {
                int n = n0 + wn + nf * 8 + 2 * tig;
                float v0 = epi_apply<EPI>(acc[nf][2 * half] + bias[n], m, n, N, extra);
                float v1 = epi_apply<EPI>(acc[nf][2 * half + 1] + bias[n + 1], m, n + 1, N, extra);
                *(float2*)&C[m * N + n] = make_float2(v0, v1);
            }
        }
        return;
    }

    float* pz = g_sp + (size_t)z * M * N;
    #pragma unroll
    for (int half = 0; half < 2; half++) {
        int m = m0 + wm + g + half * 8;
        #pragma unroll
        for (int nf = 0; nf < 2; nf++) {
            int n = n0 + wn + nf * 8 + 2 * tig;
            *(float2*)&pz[m * N + n] = make_float2(acc[nf][2 * half], acc[nf][2 * half + 1]);
        }
    }
    __threadfence();
    __syncthreads();
    __shared__ unsigned s_old;
    const int tile = blockIdx.y * gridDim.x + blockIdx.x;
    if (t == 0) s_old = atomicAdd(&g_cnt[tile], 1);
    __syncthreads();
    if (s_old != (unsigned)(S - 1)) return;
    __threadfence();

    #pragma unroll
    for (int half = 0; half < 2; half++) {
        int m = m0 + wm + g + half * 8;
        #pragma unroll
        for (int nf = 0; nf < 2; nf++) {
            int n = n0 + wn + nf * 8 + 2 * tig;
            float v0 = bias[n], v1 = bias[n + 1];
            for (int s2 = 0; s2 < S; s2++) {
                float2 pv = *(const float2*)&g_sp[(size_t)s2 * M * N + m * N + n];
                v0 += pv.x; v1 += pv.y;
            }
            v0 = epi_apply<EPI>(v0, m, n, N, extra);
            v1 = epi_apply<EPI>(v1, m, n + 1, N, extra);
            *(float2*)&C[m * N + n] = make_float2(v0, v1);
        }
    }
    if (t == 0) g_cnt[tile] = 0;
}

// ---------------- GEMM B: 64x64 tile, 2-stage cp.async (SMEM-limited) ----------
template <int EPI>
__global__ void __launch_bounds__(256) gemm64_k(
    const float* __restrict__ A, const float* __restrict__ B,
    const float* __restrict__ bias, const float* __restrict__ extra,
    float* __restrict__ C, int M, int N, int K, int S, int Kc) {
    __shared__ __align__(16) unsigned As[2][64][36];
    __shared__ __align__(16) unsigned Bs[2][32][68];

    const int t = threadIdx.x;
    const int m0 = blockIdx.y * 64, n0 = blockIdx.x * 64;
    const int z = blockIdx.z;
    const int kb0 = z * Kc;
    const int warp = t >> 5, lane = t & 31;
    const int g = lane >> 2, tig = lane & 3;
    const int wm = (warp >> 2) * 32;
    const int wn = (warp & 3) * 16;

    float acc[2][2][4];
    #pragma unroll
    for (int mt = 0; mt < 2; mt++)
        #pragma unroll
        for (int nf = 0; nf < 2; nf++)
            #pragma unroll
            for (int r = 0; r < 4; r++) acc[mt][nf][r] = 0.f;

    const int a_row = t >> 2, a_colb = (t & 3) * 8;
    const int b_row = t >> 3, b_colb = (t & 7) * 8;
    const int NC = Kc >> 5;
    const float* Ab = A + kb0 + (size_t)(m0 + a_row) * K + a_colb;
    const float* Bb = B + (size_t)(kb0 + b_row) * N + n0 + b_colb;

    cpasync16(&As[0][a_row][a_colb], Ab);
    cpasync16(&As[0][a_row][a_colb + 4], Ab + 4);
    cpasync16(&Bs[0][b_row][b_colb], Bb);
    cpasync16(&Bs[0][b_row][b_colb + 4], Bb + 4);
    cp_commit();

    for (int c = 0; c < NC; c++) {
        const int s = c & 1;
        if (c + 1 < NC) {
            int k0 = (c + 1) * 32;
            cpasync16(&As[s ^ 1][a_row][a_colb], Ab + k0);
            cpasync16(&As[s ^ 1][a_row][a_colb + 4], Ab + k0 + 4);
            cpasync16(&Bs[s ^ 1][b_row][b_colb], Bb + (size_t)k0 * N);
            cpasync16(&Bs[s ^ 1][b_row][b_colb + 4], Bb + (size_t)k0 * N + 4);
        }
        cp_commit();
        cp_wait<1>();
        __syncthreads();

        #pragma unroll
        for (int ks = 0; ks < 4; ks++) {
            const int k8 = ks * 8;
            unsigned a[2][4], bf[2][2];
            #pragma unroll
            for (int mt = 0; mt < 2; mt++) {
                int mr = wm + mt * 16 + g;
                a[mt][0] = As[s][mr][k8 + tig];
                a[mt][1] = As[s][mr + 8][k8 + tig];
                a[mt][2] = As[s][mr][k8 + tig + 4];
                a[mt][3] = As[s][mr + 8][k8 + tig + 4];
            }
            #pragma unroll
            for (int nf = 0; nf < 2; nf++) {
                int nc = wn + nf * 8 + g;
                bf[nf][0] = Bs[s][k8 + tig][nc];
                bf[nf][1] = Bs[s][k8 + tig + 4][nc];
            }
            #pragma unroll
            for (int mt = 0; mt < 2; mt++)
                #pragma unroll
                for (int nf = 0; nf < 2; nf++)
                    mma_tf32(acc[mt][nf], a[mt][0], a[mt][1], a[mt][2], a[mt][3],
                             bf[nf][0], bf[nf][1]);
        }
        __syncthreads();
    }

    if (S == 1) {
        #pragma unroll
        for (int mt = 0; mt < 2; mt++)
            #pragma unroll
            for (int half = 0; half < 2; half++) {
                int m = m0 + wm + mt * 16 + g + half * 8;
                #pragma unroll
                for (int nf = 0; nf < 2; nf++) {
                    int n = n0 + wn + nf * 8 + 2 * tig;
                    float v0 = epi_apply<EPI>(acc[mt][nf][2 * half] + bias[n], m, n, N, extra);
                    float v1 = epi_apply<EPI>(acc[mt][nf][2 * half + 1] + bias[n + 1], m, n + 1, N, extra);
                    *(float2*)&C[m * N + n] = make_float2(v0, v1);
                }
            }
        return;
    }

    float* pz = g_sp + (size_t)z * M * N;
    #pragma unroll
    for (int mt = 0; mt < 2; mt++)
        #pragma unroll
        for (int half = 0; half < 2; half++) {
            int m = m0 + wm + mt * 16 + g + half * 8;
            #pragma unroll
            for (int nf = 0; nf < 2; nf++) {
                int n = n0 + wn + nf * 8 + 2 * tig;
                *(float2*)&pz[m * N + n] =
                    make_float2(acc[mt][nf][2 * half], acc[mt][nf][2 * half + 1]);
            }
        }
    __threadfence();
    __syncthreads();
    __shared__ unsigned s_old;
    const int tile = blockIdx.y * gridDim.x + blockIdx.x;
    if (t == 0) s_old = atomicAdd(&g_cnt[tile], 1);
    __syncthreads();
    if (s_old != (unsigned)(S - 1)) return;
    __threadfence();

    #pragma unroll
    for (int mt = 0; mt < 2; mt++)
        #pragma unroll
        for (int half = 0; half < 2; half++) {
            int m = m0 + wm + mt * 16 + g + half * 8;
            #pragma unroll
            for (int nf = 0; nf < 2; nf++) {
                int n = n0 + wn + nf * 8 + 2 * tig;
                float v0 = bias[n], v1 = bias[n + 1];
                for (int s2 = 0; s2 < S; s2++) {
                    float2 pv = *(const float2*)&g_sp[(size_t)s2 * M * N + m * N + n];
                    v0 += pv.x; v1 += pv.y;
                }
                v0 = epi_apply<EPI>(v0, m, n, N, extra);
                v1 = epi_apply<EPI>(v1, m, n + 1, N, extra);
                *(float2*)&C[m * N + n] = make_float2(v0, v1);
            }
        }
    if (t == 0) g_cnt[tile] = 0;
}

// ---------------- layernorm: one warp per row, shuffle reductions ----------------
__global__ void __launch_bounds__(256) ln_k(
    const float* __restrict__ in, const float* __restrict__ gw,
    const float* __restrict__ bw, float* __restrict__ out) {
    const int t = threadIdx.x, warp = t >> 5, lane = t & 31;
    const int row = blockIdx.x * 8 + warp;
    const float4* r = (const float4*)(in + row * 256);
    float4 v0 = r[lane], v1 = r[lane + 32];
    float s = v0.x + v0.y + v0.z + v0.w + v1.x + v1.y + v1.z + v1.w;
    #pragma unroll
    for (int o = 16; o > 0; o >>= 1) s += __shfl_xor_sync(0xffffffffu, s, o);
    float mu = s * (1.f / 256.f);
    float d0x = v0.x - mu, d0y = v0.y - mu, d0z = v0.z - mu, d0w = v0.w - mu;
    float d1x = v1.x - mu, d1y = v1.y - mu, d1z = v1.z - mu, d1w = v1.w - mu;
    float ss = d0x * d0x + d0y * d0y + d0z * d0z + d0w * d0w
             + d1x * d1x + d1y * d1y + d1z * d1z + d1w * d1w;
    #pragma unroll
    for (int o = 16; o > 0; o >>= 1) ss += __shfl_xor_sync(0xffffffffu, ss, o);
    float inv = rsqrtf(ss * (1.f / 256.f) + 1e-5f);
    const float4* g4 = (const float4*)gw;
    const float4* b4 = (const float4*)bw;
    float4 ga = g4[lane], gb = g4[lane + 32];
    float4 ba = b4[lane], bb = b4[lane + 32];
    float4* o4 = (float4*)(out + row * 256);
    o4[lane] = make_float4(d0x * inv * ga.x + ba.x, d0y * inv * ga.y + ba.y,
                           d0z * inv * ga.z + ba.z, d0w * inv * ga.w + ba.w);
    o4[lane + 32] = make_float4(d1x * inv * gb.x + bb.x, d1y * inv * gb.y + bb.y,
                                d1z * inv * gb.z + bb.z, d1w * inv * gb.w + bb.w);
}

// ---------------- causal attention: 2 threads/query, 3-stage ring, 1 sync/tile --
__global__ void __launch_bounds__(128) attn_k(const float* __restrict__ c,
                                              float* __restrict__ x) {
    __shared__ __align__(16) float Ks[3][32][32];
    __shared__ __align__(16) float Vs[3][32][32];
    const int t = threadIdx.x;            // 128 threads
    const int qt = blockIdx.x;            // 8 query tiles of 64
    const int bh = blockIdx.y;            // 16 (b,h)
    const int b = bh >> 3, h = bh & 7;
    const int qi = qt * 64 + (t & 63);
    const int dhalf = t >> 6;             // 0 or 1: V dims [dhalf*16, +16)
    const float* crow = c + (b * 512 + qi) * 768 + h * 32;

    const float SC = 0.17677669529663687f;  // 1/sqrt(32)
    float q[32];
    #pragma unroll
    for (int d4 = 0; d4 < 8; d4++) {
        float4 qv = *(const float4*)(crow + d4 * 4);
        q[4 * d4 + 0] = qv.x * SC;
        q[4 * d4 + 1] = qv.y * SC;
        q[4 * d4 + 2] = qv.z * SC;
        q[4 * d4 + 3] = qv.w * SC;
    }
    float acc[16];
    #pragma unroll
    for (int d = 0; d < 16; d++) acc[d] = 0.f;
    float mrun = -1e30f, l = 0.f;

    const int ntiles = qt * 2 + 2;        // covers kb = 0..qt*64+32
    const int jj = t >> 2, q8 = (t & 3) * 8;
    const float* kvbase = c + ((size_t)b * 512 + jj) * 768 + 256 + h * 32 + q8;

    // prologue: tiles 0 and 1
    cpasync16(&Ks[0][jj][q8], kvbase);
    cpasync16(&Ks[0][jj][q8 + 4], kvbase + 4);
    cpasync16(&Vs[0][jj][q8], kvbase + 256);
    cpasync16(&Vs[0][jj][q8 + 4], kvbase + 260);
    cp_commit();
    if (ntiles > 1) {
        const float* kr = kvbase + (size_t)32 * 768;
        cpasync16(&Ks[1][jj][q8], kr);
        cpasync16(&Ks[1][jj][q8 + 4], kr + 4);
        cpasync16(&Vs[1][jj][q8], kr + 256);
        cpasync16(&Vs[1][jj][q8 + 4], kr + 260);
    }
    cp_commit();

    for (int ti = 0; ti < ntiles; ti++) {
        const int s = ti % 3;
        cp_wait<1>();
        __syncthreads();
        if (ti + 2 < ntiles) {
            const int st = (ti + 2) % 3;
            const float* kr = kvbase + (size_t)(ti + 2) * 32 * 768;
            cpasync16(&Ks[st][jj][q8], kr);
            cpasync16(&Ks[st][jj][q8 + 4], kr + 4);
            cpasync16(&Vs[st][jj][q8], kr + 256);
            cpasync16(&Vs[st][jj][q8 + 4], kr + 260);
        }
        cp_commit();

        const int kb = ti * 32;
        if (kb <= qi) {
            int jmax = qi - kb;
            if (jmax > 31) jmax = 31;
            float sarr[32];
            float tmax = -1e30f;
            #pragma unroll
            for (int j = 0; j < 32; j++) {
                if (j <= jmax) {
                    float sc = 0.f;
                    #pragma unroll
                    for (int d = 0; d < 32; d++) sc += q[d] * Ks[s][j][d];
                    sarr[j] = sc;
                    tmax = fmaxf(tmax, sc);
                }
            }
            float newm = fmaxf(mrun, tmax);
            float alpha = __expf(mrun - newm);
            l *= alpha;
            #pragma unroll
            for (int d = 0; d < 16; d++) acc[d] *= alpha;
            #pragma unroll
            for (int j = 0; j < 32; j++) {
                if (j <= jmax) {
                    float p = __expf(sarr[j] - newm);
                    l += p;
                    #pragma unroll
                    for (int d = 0; d < 16; d++) acc[d] += p * Vs[s][j][dhalf * 16 + d];
                }
            }
            mrun = newm;
        }
    }
    float inv = 1.f / l;
    float* xr = x + (b * 512 + qi) * 256 + h * 32 + dhalf * 16;
    #pragma unroll
    for (int d = 0; d < 16; d++) xr[d] += acc[d] * inv;
}

// ---------------- deterministic global mean/std (ddof=1) + normalize ------------
__global__ void reduce_k(const float* __restrict__ e) {
    __shared__ double s1[256], s2[256];
    const int t = threadIdx.x;
    double s = 0.0, ss = 0.0;
    for (int i = blockIdx.x * 256 + t; i < 262144; i += 256 * 256) {
        double v = (double)e[i];
        s += v;
        ss += v * v;
    }
    s1[t] = s;
    s2[t] = ss;
    __syncthreads();
    for (int k = 128; k > 0; k >>= 1) {
        if (t < k) { s1[t] += s1[t + k]; s2[t] += s2[t + k]; }
        __syncthreads();
    }
    if (t == 0) { g_part[blockIdx.x] = s1[0]; g_part[256 + blockIdx.x] = s2[0]; }
}

__global__ void norm_k(float* e) {
    __shared__ double s1[256], s2[256];
    const int t = threadIdx.x;
    s1[t] = g_part[t];
    s2[t] = g_part[256 + t];
    __syncthreads();
    for (int k = 128; k > 0; k >>= 1) {
        if (t < k) { s1[t] += s1[t + k]; s2[t] += s2[t + k]; }
        __syncthreads();
    }
    const double n = 262144.0;
    double mu = s1[0] / n;
    double var = (s2[0] - n * mu * mu) / (n - 1.0);
    float inv = (float)(1.0 / sqrt(var));
    float fmu = (float)mu;
    int i = (blockIdx.x * 256 + t) * 4;
    float4 v = *(float4*)&e[i];
    v.x = (v.x - fmu) * inv + 1e-10f;
    v.y = (v.y - fmu) * inv + 1e-10f;
    v.z = (v.z - fmu) * inv + 1e-10f;
    v.w = (v.w - fmu) * inv + 1e-10f;
    *(float4*)&e[i] = v;
}

// ---------------- launch ----------------
extern "C" void kernel_launch(void* const* d_in, const int* in_sizes, int n_in,
                              void* d_out, int out_size) {
    const float* state   = (const float*)d_in[0];
    const float* conv_w1 = (const float*)d_in[1];
    const float* conv_b1 = (const float*)d_in[2];
    const float* conv_w2 = (const float*)d_in[3];
    const float* conv_b2 = (const float*)d_in[4];
    const float* conv_w3 = (const float*)d_in[5];
    const float* conv_b3 = (const float*)d_in[6];
    const float* pre_w   = (const float*)d_in[7];
    const float* pre_b   = (const float*)d_in[8];
    const float* pos_w   = (const float*)d_in[9];
    const float* ln1_g   = (const float*)d_in[10];
    const float* ln1_b   = (const float*)d_in[11];
    const float* enc_w   = (const float*)d_in[12];
    const float* enc_b   = (const float*)d_in[13];
    const float* ln2_g   = (const float*)d_in[14];
    const float* ln2_b   = (const float*)d_in[15];
    const float* ffn_w1  = (const float*)d_in[16];
    const float* ffn_b1  = (const float*)d_in[17];
    const float* ffn_w2  = (const float*)d_in[18];
    const float* ffn_b2  = (const float*)d_in[19];
    const float* emb_w   = (const float*)d_in[20];
    const float* emb_b   = (const float*)d_in[21];
    float* out = (float*)d_out;

    float *x1, *x2, *x3, *x, *xn, *cb, *hb;
    cudaGetSymbolAddress((void**)&x1, g_x1);
    cudaGetSymbolAddress((void**)&x2, g_x2);
    cudaGetSymbolAddress((void**)&x3, g_x3);
    cudaGetSymbolAddress((void**)&x,  g_x);
    cudaGetSymbolAddress((void**)&xn, g_xn);
    cudaGetSymbolAddress((void**)&cb, g_c);
    cudaGetSymbolAddress((void**)&hb, g_h);

    // conv stem: all three tensorized implicit GEMM
    conv1t_k<<<dim3(12, 1024), 256>>>(state, conv_w1, conv_b1, x1);
    convt_k<48, 60, 24, 30, 8><<<1024, 256>>>(x1, conv_w2, conv_b2, x2);
    convt_k<24, 30, 12, 15, 4><<<1024, 128>>>(x2, conv_w3, conv_b3, x3);

    // pre-projection + positional  (64x64 tiles, S=9, cp.async)
    gemm64_k<1><<<dim3(4, 16, 9), 256>>>(x3, pre_w, pre_b, pos_w, x,
                                         1024, 256, 2880, 9, 320);

    for (int k = 0; k < 4; k++) {
        ln_k<<<128, 256>>>(x, ln1_g + k * 256, ln1_b + k * 256, xn);
        gemm32_k<0><<<dim3(12, 32, 2), 256>>>(xn, enc_w + k * 256 * 768, enc_b + k * 768,
                                              nullptr, cb, 1024, 768, 256, 2, 128);
        attn_k<<<dim3(8, 16), 128>>>(cb, x);
        ln_k<<<128, 256>>>(x, ln2_g + k * 256, ln2_b + k * 256, x);
        gemm32_k<2><<<dim3(16, 32, 2), 256>>>(x, ffn_w1 + k * 256 * 1024, ffn_b1 + k * 1024,
                                              nullptr, hb, 1024, 1024, 256, 2, 128);
        gemm32_k<3><<<dim3(4, 32, 4), 256>>>(hb, ffn_w2 + k * 1024 * 256, ffn_b2 + k * 256,
                                             x, x, 1024, 256, 1024, 4, 256);
    }

    gemm32_k<0><<<dim3(4, 32, 4), 256>>>(x, emb_w, emb_b, nullptr, out,
                                         1024, 256, 256, 4, 64);

    reduce_k<<<256, 256>>>(out);
    norm_k<<<256, 256>>>(out);
}